// round 4
// baseline (speedup 1.0000x reference)
#include <cuda_runtime.h>
#include <cstdint>
#include <math.h>

#define C_CLS 1000
#define CP    1024
#define AD    512
#define HD    256
#define NMAX  131072

// ---------------- scratch ----------------------------------------------------
__device__ float g_attr[CP * AD];      // padded attributes [CP,AD]
__device__ float g_attrT[AD * CP];     // attr^T [AD,CP]
__device__ float g_p[CP * HD];
__device__ float g_d[CP * CP];
__device__ float g_A[CP * CP];
__device__ float g_enc[CP * AD];
__device__ float g_q[CP * HD];
__device__ float g_mean[C_CLS * AD];
__device__ float g_protos[CP * AD];
__device__ float g_protT[AD * CP];
__device__ float g_hT[HD * AD];
__device__ float g_gT[HD * AD];
__device__ int   g_counts[C_CLS];
__device__ int   g_offsets[C_CLS];
__device__ int   g_cursor[C_CLS];
__device__ int   g_sorted[NMAX];

// ---------------- small helpers ----------------------------------------------
__device__ __forceinline__ float warpSum(float v) {
#pragma unroll
    for (int o = 16; o; o >>= 1) v += __shfl_xor_sync(0xffffffffu, v, o);
    return v;
}
__device__ __forceinline__ float warpMax(float v) {
#pragma unroll
    for (int o = 16; o; o >>= 1) v = fmaxf(v, __shfl_xor_sync(0xffffffffu, v, o));
    return v;
}
__device__ __forceinline__ float blockSum(float v, float* sh) {
    int t = threadIdx.x, lane = t & 31, w = t >> 5, nw = blockDim.x >> 5;
    v = warpSum(v);
    if (!lane) sh[w] = v;
    __syncthreads();
    if (w == 0) {
        float x = (lane < nw) ? sh[lane] : 0.f;
        x = warpSum(x);
        if (!lane) sh[0] = x;
    }
    __syncthreads();
    float r = sh[0];
    __syncthreads();
    return r;
}
__device__ __forceinline__ float blockMax(float v, float* sh) {
    int t = threadIdx.x, lane = t & 31, w = t >> 5, nw = blockDim.x >> 5;
    v = warpMax(v);
    if (!lane) sh[w] = v;
    __syncthreads();
    if (w == 0) {
        float x = (lane < nw) ? sh[lane] : -1e30f;
        x = warpMax(x);
        if (!lane) sh[0] = x;
    }
    __syncthreads();
    float r = sh[0];
    __syncthreads();
    return r;
}
__device__ __forceinline__ uint32_t f2tf32(float x) {
    uint32_t r;
    asm("cvt.rna.tf32.f32 %0, %1;" : "=r"(r) : "f"(x));
    return r;
}

// ---------------- proto pipeline ---------------------------------------------
__global__ void zero_counts_k() {
    int i = blockIdx.x * blockDim.x + threadIdx.x;
    if (i < C_CLS) { g_counts[i] = 0; g_cursor[i] = 0; }
}
__global__ __launch_bounds__(256) void hist_k(const int* __restrict__ labels, int n) {
    __shared__ int h[C_CLS];
    for (int i = threadIdx.x; i < C_CLS; i += 256) h[i] = 0;
    __syncthreads();
    for (int i = blockIdx.x * blockDim.x + threadIdx.x; i < n; i += gridDim.x * blockDim.x)
        atomicAdd(&h[labels[i]], 1);
    __syncthreads();
    for (int i = threadIdx.x; i < C_CLS; i += 256)
        if (h[i]) atomicAdd(&g_counts[i], h[i]);
}
__global__ void scan_k() {
    __shared__ int s[1024];
    int t = threadIdx.x;
    int c = (t < C_CLS) ? g_counts[t] : 0;
    s[t] = c;
    __syncthreads();
    for (int off = 1; off < 1024; off <<= 1) {
        int v = (t >= off) ? s[t - off] : 0;
        __syncthreads();
        s[t] += v;
        __syncthreads();
    }
    if (t < C_CLS) g_offsets[t] = s[t] - c;
}
#define SCAT_E 16
__global__ __launch_bounds__(256) void scatter_k(const int* __restrict__ labels, int n) {
    __shared__ int h[C_CLS];
    __shared__ int base[C_CLS];
    for (int i = threadIdx.x; i < C_CLS; i += 256) h[i] = 0;
    __syncthreads();
    int start = blockIdx.x * (256 * SCAT_E);
    int lab[SCAT_E], lr[SCAT_E];
#pragma unroll
    for (int j = 0; j < SCAT_E; j++) {
        int i = start + j * 256 + threadIdx.x;
        if (i < n) { lab[j] = labels[i]; lr[j] = atomicAdd(&h[lab[j]], 1); }
        else lab[j] = -1;
    }
    __syncthreads();
    for (int c = threadIdx.x; c < C_CLS; c += 256)
        base[c] = h[c] ? atomicAdd(&g_cursor[c], h[c]) : 0;
    __syncthreads();
#pragma unroll
    for (int j = 0; j < SCAT_E; j++)
        if (lab[j] >= 0)
            g_sorted[g_offsets[lab[j]] + base[lab[j]] + lr[j]] = start + j * 256 + threadIdx.x;
}
__global__ __launch_bounds__(128) void class_mean_k(const float* __restrict__ img) {
    int c = blockIdx.x;
    int t = threadIdx.x;
    int cnt = g_counts[c], off = g_offsets[c];
    __shared__ int idx[256];
    int lim = cnt < 256 ? cnt : 256;
    for (int j = t; j < lim; j += 128) idx[j] = g_sorted[off + j];
    __syncthreads();
    float4 acc = make_float4(0.f, 0.f, 0.f, 0.f);
    int j = 0;
    for (; j + 4 <= lim; j += 4) {
        float4 a = ((const float4*)(img + (size_t)idx[j] * AD))[t];
        float4 b = ((const float4*)(img + (size_t)idx[j + 1] * AD))[t];
        float4 d = ((const float4*)(img + (size_t)idx[j + 2] * AD))[t];
        float4 e = ((const float4*)(img + (size_t)idx[j + 3] * AD))[t];
        acc.x += a.x + b.x + d.x + e.x;
        acc.y += a.y + b.y + d.y + e.y;
        acc.z += a.z + b.z + d.z + e.z;
        acc.w += a.w + b.w + d.w + e.w;
    }
    for (; j < lim; j++) {
        float4 a = ((const float4*)(img + (size_t)idx[j] * AD))[t];
        acc.x += a.x; acc.y += a.y; acc.z += a.z; acc.w += a.w;
    }
    for (j = 256; j < cnt; j++) {
        float4 a = ((const float4*)(img + (size_t)g_sorted[off + j] * AD))[t];
        acc.x += a.x; acc.y += a.y; acc.z += a.z; acc.w += a.w;
    }
    float inv = cnt > 0 ? 1.f / (float)cnt : 0.f;
    ((float4*)(g_mean + (size_t)c * AD))[t] =
        make_float4(acc.x * inv, acc.y * inv, acc.z * inv, acc.w * inv);
}
__global__ void gather_protos_k(const int* __restrict__ tpl) {
    int i = blockIdx.x, t = threadIdx.x;
    float4 v = make_float4(0.f, 0.f, 0.f, 0.f);
    if (i < C_CLS) v = ((const float4*)(g_mean + (size_t)tpl[i] * AD))[t];
    ((float4*)(g_protos + (size_t)i * AD))[t] = v;
}
__global__ void pad_attr_k(const float* __restrict__ attrs) {
    int i = blockIdx.x, t = threadIdx.x;
    float4 v = make_float4(0.f, 0.f, 0.f, 0.f);
    if (i < C_CLS) v = ((const float4*)(attrs + (size_t)i * AD))[t];
    ((float4*)(g_attr + (size_t)i * AD))[t] = v;
}

// ---------------- transpose --------------------------------------------------
__global__ __launch_bounds__(256) void transpose_k(const float* __restrict__ in,
                                                   float* __restrict__ out,
                                                   int R, int Ccol) {
    __shared__ float t[32][33];
    int bx = blockIdx.x * 32, by = blockIdx.y * 32;
    int x = bx + threadIdx.x;
    int y = by + threadIdx.y;
#pragma unroll
    for (int i = 0; i < 32; i += 8) t[threadIdx.y + i][threadIdx.x] = in[(size_t)(y + i) * Ccol + x];
    __syncthreads();
    x = by + threadIdx.x;
    y = bx + threadIdx.y;
#pragma unroll
    for (int i = 0; i < 32; i += 8) out[(size_t)(y + i) * R + x] = t[threadIdx.x][threadIdx.y + i];
}

// ---------------- tf32 mma.sync NT GEMM: C[M,N]=A[M,K]@B[N,K]^T --------------
// 64x64 CTA tile, 128 threads (2x2 warps of 32x32), K-chunk 32, double buffer.
// smem stride 36 floats -> fragment gathers are bank-conflict-free.
#define KCH 32
#define SSTR 36

__device__ __forceinline__ void mma_tf32(float* c, const uint32_t* a, const uint32_t* b) {
    asm volatile(
        "mma.sync.aligned.m16n8k8.row.col.f32.tf32.tf32.f32 "
        "{%0,%1,%2,%3}, {%4,%5,%6,%7}, {%8,%9}, {%0,%1,%2,%3};"
        : "+f"(c[0]), "+f"(c[1]), "+f"(c[2]), "+f"(c[3])
        : "r"(a[0]), "r"(a[1]), "r"(a[2]), "r"(a[3]), "r"(b[0]), "r"(b[1]));
}

__global__ __launch_bounds__(128) void mma_gemm_k(const float* __restrict__ A,
                                                  const float* __restrict__ B,
                                                  float* __restrict__ Cc,
                                                  int N, int K, int mstore) {
    __shared__ float As[2][64][SSTR];
    __shared__ float Bs[2][64][SSTR];
    const int tid = threadIdx.x;
    const int wid = tid >> 5, lane = tid & 31;
    const int gid = lane >> 2, tig = lane & 3;
    const int m0 = blockIdx.y * 64, n0 = blockIdx.x * 64;
    const int wm = (wid & 1) * 32, wn = (wid >> 1) * 32;

    const int lrow = tid >> 1;            // 0..63
    const int lq = (tid & 1) * 4;         // 0 or 4 (float4 slot within 8)
    // each thread loads 2 float4 for A and 2 for B per chunk (64 rows x 8 float4)
    float acc[2][4][4];
#pragma unroll
    for (int i = 0; i < 2; i++)
#pragma unroll
        for (int j = 0; j < 4; j++)
#pragma unroll
            for (int k = 0; k < 4; k++) acc[i][j][k] = 0.f;

    const int nchunks = K >> 5;
    float4 ra[2], rb[2];

    // prologue: load chunk 0
#pragma unroll
    for (int i = 0; i < 2; i++) {
        int row = lrow, kq = lq + 0;      // two float4: columns lq and lq+? use i for col-half
        int col4 = (tid & 1) * 4 + 0;     // unused
        (void)row; (void)kq; (void)col4;
    }
    {
#pragma unroll
        for (int i = 0; i < 2; i++) {
            int idx = tid + i * 128;          // 0..255
            int row = idx >> 2;               // 0..63
            int kq = (idx & 3) * 8;           // 0,8,16,24
            ra[i] = *(const float4*)(A + (size_t)(m0 + row) * K + kq);
            rb[i] = *(const float4*)(B + (size_t)(n0 + row) * K + kq);
        }
        // note: (idx&3)*8 covers k 0..31 in float4 pairs? 4 groups * 8 floats needs 2 float4 each.
    }
    // The above covers only half the chunk; redo with a clean 4-load scheme below.

#pragma unroll
    for (int c = 0; c < 1; c++) {}        // (placeholder removed by compiler)

    // ---- clean loader: 64 rows x 32 k = 512 float4; 128 threads x 4 ----
    auto load_chunk = [&](int kc, int buf) {
#pragma unroll
        for (int i = 0; i < 4; i++) {
            int idx = tid + i * 128;          // 0..511
            int row = idx >> 3;               // 0..63
            int kq = (idx & 7) * 4;           // 0..28
            float4 va = *(const float4*)(A + (size_t)(m0 + row) * K + kc * KCH + kq);
            float4 vb = *(const float4*)(B + (size_t)(n0 + row) * K + kc * KCH + kq);
            float* da = &As[buf][row][kq];
            float* db = &Bs[buf][row][kq];
            da[0] = __uint_as_float(f2tf32(va.x));
            da[1] = __uint_as_float(f2tf32(va.y));
            da[2] = __uint_as_float(f2tf32(va.z));
            da[3] = __uint_as_float(f2tf32(va.w));
            db[0] = __uint_as_float(f2tf32(vb.x));
            db[1] = __uint_as_float(f2tf32(vb.y));
            db[2] = __uint_as_float(f2tf32(vb.z));
            db[3] = __uint_as_float(f2tf32(vb.w));
        }
    };
    auto compute_chunk = [&](int buf) {
#pragma unroll
        for (int ks = 0; ks < 4; ks++) {
            uint32_t af[2][4], bf[4][2];
#pragma unroll
            for (int mf = 0; mf < 2; mf++) {
                int r = wm + mf * 16 + gid;
                af[mf][0] = __float_as_uint(As[buf][r][ks * 8 + tig]);
                af[mf][1] = __float_as_uint(As[buf][r + 8][ks * 8 + tig]);
                af[mf][2] = __float_as_uint(As[buf][r][ks * 8 + tig + 4]);
                af[mf][3] = __float_as_uint(As[buf][r + 8][ks * 8 + tig + 4]);
            }
#pragma unroll
            for (int nf = 0; nf < 4; nf++) {
                int r = wn + nf * 8 + gid;
                bf[nf][0] = __float_as_uint(Bs[buf][r][ks * 8 + tig]);
                bf[nf][1] = __float_as_uint(Bs[buf][r][ks * 8 + tig + 4]);
            }
#pragma unroll
            for (int mf = 0; mf < 2; mf++)
#pragma unroll
                for (int nf = 0; nf < 4; nf++) mma_tf32(acc[mf][nf], af[mf], bf[nf]);
        }
    };

    load_chunk(0, 0);
    __syncthreads();
    for (int c = 0; c < nchunks; c++) {
        int buf = c & 1;
        compute_chunk(buf);
        if (c + 1 < nchunks) load_chunk(c + 1, buf ^ 1);
        __syncthreads();
    }

    // epilogue
#pragma unroll
    for (int mf = 0; mf < 2; mf++) {
#pragma unroll
        for (int nf = 0; nf < 4; nf++) {
            int col = n0 + wn + nf * 8 + tig * 2;
            int r0 = m0 + wm + mf * 16 + gid;
            if (r0 < mstore)
                *(float2*)(Cc + (size_t)r0 * N + col) = make_float2(acc[mf][nf][0], acc[mf][nf][1]);
            int r1 = r0 + 8;
            if (r1 < mstore)
                *(float2*)(Cc + (size_t)r1 * N + col) = make_float2(acc[mf][nf][2], acc[mf][nf][3]);
        }
    }
}

// ---------------- row normalize & masked softmax -----------------------------
__global__ __launch_bounds__(256) void rownorm_k(float* __restrict__ P) {
    __shared__ float sh[32];
    int r = blockIdx.x;
    float* row = P + (size_t)r * HD;
    float x = row[threadIdx.x];
    float ss = blockSum(x * x, sh);
    row[threadIdx.x] = x * rsqrtf(fmaxf(ss, 1e-30f));
}

__global__ __launch_bounds__(256) void masked_softmax_k(const float* __restrict__ D,
                                                        float* __restrict__ O) {
    __shared__ float sh[32];
    int r = blockIdx.x;
    const float* din = D + (size_t)r * CP;
    float* o = O + (size_t)r * CP;
    int t = threadIdx.x;
    if (r >= C_CLS) {
        for (int c = t; c < CP; c += 256) o[c] = 0.f;
        return;
    }
    float v[4];
    float mx = -1e30f;
#pragma unroll
    for (int j = 0; j < 4; j++) {
        int c = t + j * 256;
        float x = (c < C_CLS) ? din[c] : -1e30f;
        v[j] = x;
        if (x > 0.5f) mx = fmaxf(mx, x);
    }
    mx = blockMax(mx, sh);
    float m10 = mx * 10.f;
    float e[4];
    float s = 0.f;
#pragma unroll
    for (int j = 0; j < 4; j++) {
        e[j] = (v[j] > 0.5f) ? expf(v[j] * 10.f - m10) : 0.f;
        s += e[j];
    }
    s = blockSum(s, sh);
    float inv = 1.f / s;
#pragma unroll
    for (int j = 0; j < 4; j++) {
        int c = t + j * 256;
        o[c] = (c < C_CLS) ? e[j] * inv : 0.f;
    }
}

// ---------------- launch ------------------------------------------------------
static float* symf(const void* p) { return (float*)p; }

extern "C" void kernel_launch(void* const* d_in, const int* in_sizes, int n_in,
                              void* d_out, int out_size) {
    const float* img    = (const float*)d_in[0];
    const float* attrs  = (const float*)d_in[1];
    const float* att_g  = (const float*)d_in[2];
    const float* att_h  = (const float*)d_in[3];
    const int*   labels = (const int*)d_in[4];
    const int*   tpl    = (const int*)d_in[5];
    float* out = (float*)d_out;
    int N = in_sizes[4];
    (void)n_in; (void)out_size;

    void *p_attr, *p_attrT, *p_p, *p_d, *p_A, *p_enc, *p_q, *p_prot, *p_protT, *p_hT, *p_gT;
    cudaGetSymbolAddress(&p_attr, g_attr);
    cudaGetSymbolAddress(&p_attrT, g_attrT);
    cudaGetSymbolAddress(&p_p, g_p);
    cudaGetSymbolAddress(&p_d, g_d);
    cudaGetSymbolAddress(&p_A, g_A);
    cudaGetSymbolAddress(&p_enc, g_enc);
    cudaGetSymbolAddress(&p_q, g_q);
    cudaGetSymbolAddress(&p_prot, g_protos);
    cudaGetSymbolAddress(&p_protT, g_protT);
    cudaGetSymbolAddress(&p_hT, g_hT);
    cudaGetSymbolAddress(&p_gT, g_gT);
    float *A_attr = symf(p_attr), *A_attrT = symf(p_attrT), *A_p = symf(p_p),
          *A_d = symf(p_d), *A_A = symf(p_A), *A_enc = symf(p_enc), *A_q = symf(p_q),
          *A_prot = symf(p_prot), *A_protT = symf(p_protT), *A_hT = symf(p_hT),
          *A_gT = symf(p_gT);

    // --- proto pipeline ---
    zero_counts_k<<<4, 256>>>();
    hist_k<<<25, 256>>>(labels, N);
    scan_k<<<1, 1024>>>();
    scatter_k<<<(N + 256 * SCAT_E - 1) / (256 * SCAT_E), 256>>>(labels, N);
    class_mean_k<<<C_CLS, 128>>>(img);
    gather_protos_k<<<CP, 128>>>(tpl);

    // --- prepare operands ---
    pad_attr_k<<<CP, 128>>>(attrs);
    transpose_k<<<dim3(HD / 32, AD / 32), dim3(32, 8)>>>(att_h, A_hT, AD, HD);
    transpose_k<<<dim3(HD / 32, AD / 32), dim3(32, 8)>>>(att_g, A_gT, AD, HD);
    transpose_k<<<dim3(AD / 32, CP / 32), dim3(32, 8)>>>(A_attr, A_attrT, CP, AD);
    transpose_k<<<dim3(AD / 32, CP / 32), dim3(32, 8)>>>(A_prot, A_protT, CP, AD);

    // --- attribute chain (all NT tf32 HMMA GEMMs) ---
    mma_gemm_k<<<dim3(HD / 64, CP / 64), 128>>>(A_attr, A_hT, A_p, HD, AD, CP);
    rownorm_k<<<CP, HD>>>(A_p);
    mma_gemm_k<<<dim3(CP / 64, CP / 64), 128>>>(A_p, A_p, A_d, CP, HD, CP);
    masked_softmax_k<<<CP, 256>>>(A_d, A_A);
    mma_gemm_k<<<dim3(AD / 64, CP / 64), 128>>>(A_A, A_attrT, A_enc, AD, CP, CP);
    mma_gemm_k<<<dim3(HD / 64, CP / 64), 128>>>(A_enc, A_gT, A_q, HD, AD, CP);
    rownorm_k<<<CP, HD>>>(A_q);
    mma_gemm_k<<<dim3(CP / 64, CP / 64), 128>>>(A_q, A_q, A_d, CP, HD, CP);
    masked_softmax_k<<<CP, 256>>>(A_d, A_A);
    mma_gemm_k<<<dim3(AD / 64, CP / 64), 128>>>(A_A, A_protT, out, AD, CP, C_CLS);
}

// round 5
// speedup vs baseline: 1.9572x; 1.9572x over previous
#include <cuda_runtime.h>
#include <cstdint>
#include <math.h>

#define C_CLS 1000
#define CP    1024
#define AD    512
#define HD    256
#define NMAX  131072
#define KCH   32
#define SSTR  36
#define GSMEM ((2*128*SSTR + 2*64*SSTR) * 4)

// ---------------- scratch ----------------------------------------------------
__device__ float g_attr[CP * AD];
__device__ float g_attrT[AD * CP];
__device__ float g_p[CP * HD];
__device__ float g_d[CP * CP];
__device__ float g_A[CP * CP];
__device__ float g_enc[CP * AD];
__device__ float g_q[CP * HD];
__device__ float g_mean[C_CLS * AD];
__device__ float g_protT[AD * CP];
__device__ float g_hT[HD * AD];
__device__ float g_gT[HD * AD];
__device__ int   g_counts[C_CLS];
__device__ int   g_offsets[C_CLS];
__device__ int   g_cursor[C_CLS];
__device__ int   g_sorted[NMAX];

// ---------------- helpers ----------------------------------------------------
__device__ __forceinline__ float warpSum(float v) {
#pragma unroll
    for (int o = 16; o; o >>= 1) v += __shfl_xor_sync(0xffffffffu, v, o);
    return v;
}
__device__ __forceinline__ float warpMax(float v) {
#pragma unroll
    for (int o = 16; o; o >>= 1) v = fmaxf(v, __shfl_xor_sync(0xffffffffu, v, o));
    return v;
}
__device__ __forceinline__ float blockSum(float v, float* sh) {
    int t = threadIdx.x, lane = t & 31, w = t >> 5, nw = blockDim.x >> 5;
    v = warpSum(v);
    if (!lane) sh[w] = v;
    __syncthreads();
    if (w == 0) {
        float x = (lane < nw) ? sh[lane] : 0.f;
        x = warpSum(x);
        if (!lane) sh[0] = x;
    }
    __syncthreads();
    float r = sh[0];
    __syncthreads();
    return r;
}
__device__ __forceinline__ float blockMax(float v, float* sh) {
    int t = threadIdx.x, lane = t & 31, w = t >> 5, nw = blockDim.x >> 5;
    v = warpMax(v);
    if (!lane) sh[w] = v;
    __syncthreads();
    if (w == 0) {
        float x = (lane < nw) ? sh[lane] : -1e30f;
        x = warpMax(x);
        if (!lane) sh[0] = x;
    }
    __syncthreads();
    float r = sh[0];
    __syncthreads();
    return r;
}
__device__ __forceinline__ uint32_t f2tf32(float x) {
    uint32_t r;
    asm("cvt.rna.tf32.f32 %0, %1;" : "=r"(r) : "f"(x));
    return r;
}
__device__ __forceinline__ void cp16(uint32_t dst, const void* src) {
    asm volatile("cp.async.ca.shared.global [%0], [%1], 16;" :: "r"(dst), "l"(src));
}
__device__ __forceinline__ void mma_tf32(float* c, const uint32_t* a, const uint32_t* b) {
    asm volatile(
        "mma.sync.aligned.m16n8k8.row.col.f32.tf32.tf32.f32 "
        "{%0,%1,%2,%3}, {%4,%5,%6,%7}, {%8,%9}, {%0,%1,%2,%3};"
        : "+f"(c[0]), "+f"(c[1]), "+f"(c[2]), "+f"(c[3])
        : "r"(a[0]), "r"(a[1]), "r"(a[2]), "r"(a[3]), "r"(b[0]), "r"(b[1]));
}

// ---------------- proto pipeline ---------------------------------------------
__global__ void zero_counts_k() {
    int i = blockIdx.x * blockDim.x + threadIdx.x;
    if (i < C_CLS) { g_counts[i] = 0; g_cursor[i] = 0; }
}
__global__ __launch_bounds__(256) void hist_k(const int* __restrict__ labels, int n) {
    __shared__ int h[C_CLS];
    for (int i = threadIdx.x; i < C_CLS; i += 256) h[i] = 0;
    __syncthreads();
    for (int i = blockIdx.x * blockDim.x + threadIdx.x; i < n; i += gridDim.x * blockDim.x)
        atomicAdd(&h[labels[i]], 1);
    __syncthreads();
    for (int i = threadIdx.x; i < C_CLS; i += 256)
        if (h[i]) atomicAdd(&g_counts[i], h[i]);
}
__global__ void scan_k() {
    __shared__ int s[1024];
    int t = threadIdx.x;
    int c = (t < C_CLS) ? g_counts[t] : 0;
    s[t] = c;
    __syncthreads();
    for (int off = 1; off < 1024; off <<= 1) {
        int v = (t >= off) ? s[t - off] : 0;
        __syncthreads();
        s[t] += v;
        __syncthreads();
    }
    if (t < C_CLS) g_offsets[t] = s[t] - c;
}
__global__ void scatter_k(const int* __restrict__ labels, int n) {
    int i = blockIdx.x * blockDim.x + threadIdx.x;
    if (i < n) {
        int l = labels[i];
        int pos = g_offsets[l] + atomicAdd(&g_cursor[l], 1);
        g_sorted[pos] = i;
    }
}
__global__ __launch_bounds__(128) void class_mean_k(const float* __restrict__ img) {
    int c = blockIdx.x;
    int t = threadIdx.x;
    int cnt = g_counts[c], off = g_offsets[c];
    __shared__ int idx[256];
    int lim = cnt < 256 ? cnt : 256;
    for (int j = t; j < lim; j += 128) idx[j] = g_sorted[off + j];
    __syncthreads();
    float4 acc = make_float4(0.f, 0.f, 0.f, 0.f);
    int j = 0;
    for (; j + 4 <= lim; j += 4) {
        float4 a = ((const float4*)(img + (size_t)idx[j] * AD))[t];
        float4 b = ((const float4*)(img + (size_t)idx[j + 1] * AD))[t];
        float4 d = ((const float4*)(img + (size_t)idx[j + 2] * AD))[t];
        float4 e = ((const float4*)(img + (size_t)idx[j + 3] * AD))[t];
        acc.x += a.x + b.x + d.x + e.x;
        acc.y += a.y + b.y + d.y + e.y;
        acc.z += a.z + b.z + d.z + e.z;
        acc.w += a.w + b.w + d.w + e.w;
    }
    for (; j < lim; j++) {
        float4 a = ((const float4*)(img + (size_t)idx[j] * AD))[t];
        acc.x += a.x; acc.y += a.y; acc.z += a.z; acc.w += a.w;
    }
    for (j = 256; j < cnt; j++) {
        float4 a = ((const float4*)(img + (size_t)g_sorted[off + j] * AD))[t];
        acc.x += a.x; acc.y += a.y; acc.z += a.z; acc.w += a.w;
    }
    float inv = cnt > 0 ? 1.f / (float)cnt : 0.f;
    ((float4*)(g_mean + (size_t)c * AD))[t] =
        make_float4(acc.x * inv, acc.y * inv, acc.z * inv, acc.w * inv);
}
__global__ void pad_attr_k(const float* __restrict__ attrs) {
    int i = blockIdx.x, t = threadIdx.x;
    float4 v = make_float4(0.f, 0.f, 0.f, 0.f);
    if (i < C_CLS) v = ((const float4*)(attrs + (size_t)i * AD))[t];
    ((float4*)(g_attr + (size_t)i * AD))[t] = v;
}

// ---------------- transposes --------------------------------------------------
// out[Ccol, Rp] = in[R, Ccol]^T padded with zeros for rows >= R
__global__ __launch_bounds__(256) void transpose_pad_k(const float* __restrict__ in,
                                                       float* __restrict__ out,
                                                       int R, int Rp, int Ccol) {
    __shared__ float t[32][33];
    int bx = blockIdx.x * 32, by = blockIdx.y * 32;
    int x = bx + threadIdx.x;
#pragma unroll
    for (int i = 0; i < 32; i += 8) {
        int y = by + threadIdx.y + i;
        t[threadIdx.y + i][threadIdx.x] = (y < R) ? in[(size_t)y * Ccol + x] : 0.f;
    }
    __syncthreads();
    x = by + threadIdx.x;
#pragma unroll
    for (int i = 0; i < 32; i += 8) {
        int y = bx + threadIdx.y + i;
        out[(size_t)y * Rp + x] = t[threadIdx.x][threadIdx.y + i];
    }
}
// protT[AD, CP] = (mean[tpl[i]])^T  (gather + transpose fused)
__global__ __launch_bounds__(256) void protT_k(const int* __restrict__ tpl) {
    __shared__ float t[32][33];
    int bx = blockIdx.x * 32, by = blockIdx.y * 32;
    int x = bx + threadIdx.x;
#pragma unroll
    for (int i = 0; i < 32; i += 8) {
        int y = by + threadIdx.y + i;
        t[threadIdx.y + i][threadIdx.x] =
            (y < C_CLS) ? g_mean[(size_t)tpl[y] * AD + x] : 0.f;
    }
    __syncthreads();
    x = by + threadIdx.x;
#pragma unroll
    for (int i = 0; i < 32; i += 8) {
        int y = bx + threadIdx.y + i;
        g_protT[(size_t)y * CP + x] = t[threadIdx.x][threadIdx.y + i];
    }
}

// ---------------- pipelined tf32 HMMA NT GEMM: C[M,N]=A[M,K]@B[N,K]^T --------
// CTA tile 128x64, 4 warps (2x2, warp tile 64x32), cp.async double buffer.
__global__ __launch_bounds__(128) void mma_gemm_k(const float* __restrict__ A,
                                                  const float* __restrict__ B,
                                                  float* __restrict__ Cc,
                                                  int N, int K, int mstore) {
    extern __shared__ float sm[];
    float* Asm = sm;                      // [2][128][SSTR]
    float* Bsm = sm + 2 * 128 * SSTR;     // [2][64][SSTR]
    const int tid = threadIdx.x, wid = tid >> 5, lane = tid & 31;
    const int gid = lane >> 2, tig = lane & 3;
    const int m0 = blockIdx.y * 128, n0 = blockIdx.x * 64;
    const int wm = (wid & 1) * 64, wn = (wid >> 1) * 32;
    const uint32_t sbase = (uint32_t)__cvta_generic_to_shared(sm);

    float acc[4][4][4];
#pragma unroll
    for (int a = 0; a < 4; a++)
#pragma unroll
        for (int b = 0; b < 4; b++)
#pragma unroll
            for (int c = 0; c < 4; c++) acc[a][b][c] = 0.f;

    const int KC = K >> 5;

    auto loadc = [&](int kc, int buf) {
        const float* Ab = A + (size_t)m0 * K + kc * KCH;
        const float* Bb = B + (size_t)n0 * K + kc * KCH;
        uint32_t as0 = sbase + (uint32_t)(buf * 128 * SSTR) * 4u;
        uint32_t bs0 = sbase + (uint32_t)(2 * 128 * SSTR + buf * 64 * SSTR) * 4u;
#pragma unroll
        for (int i = 0; i < 8; i++) {
            int idx = tid + i * 128;
            int row = idx >> 3, kq = (idx & 7) * 4;
            cp16(as0 + (uint32_t)(row * SSTR + kq) * 4u, Ab + (size_t)row * K + kq);
        }
#pragma unroll
        for (int i = 0; i < 4; i++) {
            int idx = tid + i * 128;
            int row = idx >> 3, kq = (idx & 7) * 4;
            cp16(bs0 + (uint32_t)(row * SSTR + kq) * 4u, Bb + (size_t)row * K + kq);
        }
        asm volatile("cp.async.commit_group;" ::: "memory");
    };
    auto computec = [&](int buf) {
        const float* Ab = Asm + buf * 128 * SSTR;
        const float* Bb = Bsm + buf * 64 * SSTR;
#pragma unroll
        for (int ks = 0; ks < 4; ks++) {
            const int kb = ks * 8;
            uint32_t af[4][4], bf[4][2];
#pragma unroll
            for (int mf = 0; mf < 4; mf++) {
                int r = wm + mf * 16 + gid;
                af[mf][0] = f2tf32(Ab[r * SSTR + kb + tig]);
                af[mf][1] = f2tf32(Ab[(r + 8) * SSTR + kb + tig]);
                af[mf][2] = f2tf32(Ab[r * SSTR + kb + tig + 4]);
                af[mf][3] = f2tf32(Ab[(r + 8) * SSTR + kb + tig + 4]);
            }
#pragma unroll
            for (int nf = 0; nf < 4; nf++) {
                int r = wn + nf * 8 + gid;
                bf[nf][0] = f2tf32(Bb[r * SSTR + kb + tig]);
                bf[nf][1] = f2tf32(Bb[r * SSTR + kb + tig + 4]);
            }
#pragma unroll
            for (int mf = 0; mf < 4; mf++)
#pragma unroll
                for (int nf = 0; nf < 4; nf++) mma_tf32(acc[mf][nf], af[mf], bf[nf]);
        }
    };

    loadc(0, 0);
    for (int c = 0; c < KC; c++) {
        if (c + 1 < KC) {
            loadc(c + 1, (c + 1) & 1);
            asm volatile("cp.async.wait_group 1;" ::: "memory");
        } else {
            asm volatile("cp.async.wait_group 0;" ::: "memory");
        }
        __syncthreads();
        computec(c & 1);
        __syncthreads();
    }

#pragma unroll
    for (int mf = 0; mf < 4; mf++) {
#pragma unroll
        for (int nf = 0; nf < 4; nf++) {
            int col = n0 + wn + nf * 8 + tig * 2;
            int r0 = m0 + wm + mf * 16 + gid;
            if (r0 < mstore)
                *(float2*)(Cc + (size_t)r0 * N + col) =
                    make_float2(acc[mf][nf][0], acc[mf][nf][1]);
            int r1 = r0 + 8;
            if (r1 < mstore)
                *(float2*)(Cc + (size_t)r1 * N + col) =
                    make_float2(acc[mf][nf][2], acc[mf][nf][3]);
        }
    }
}

// ---------------- row normalize & masked softmax -----------------------------
__global__ __launch_bounds__(256) void rownorm_k(float* __restrict__ P) {
    __shared__ float sh[32];
    int r = blockIdx.x;
    float* row = P + (size_t)r * HD;
    float x = row[threadIdx.x];
    float ss = blockSum(x * x, sh);
    row[threadIdx.x] = x * rsqrtf(fmaxf(ss, 1e-30f));
}
__global__ __launch_bounds__(256) void masked_softmax_k(const float* __restrict__ D,
                                                        float* __restrict__ O) {
    __shared__ float sh[32];
    int r = blockIdx.x;
    const float* din = D + (size_t)r * CP;
    float* o = O + (size_t)r * CP;
    int t = threadIdx.x;
    if (r >= C_CLS) {
        for (int c = t; c < CP; c += 256) o[c] = 0.f;
        return;
    }
    float v[4];
    float mx = -1e30f;
#pragma unroll
    for (int j = 0; j < 4; j++) {
        int c = t + j * 256;
        float x = (c < C_CLS) ? din[c] : -1e30f;
        v[j] = x;
        if (x > 0.5f) mx = fmaxf(mx, x);
    }
    mx = blockMax(mx, sh);
    float m10 = mx * 10.f;
    float e[4];
    float s = 0.f;
#pragma unroll
    for (int j = 0; j < 4; j++) {
        e[j] = (v[j] > 0.5f) ? expf(v[j] * 10.f - m10) : 0.f;
        s += e[j];
    }
    s = blockSum(s, sh);
    float inv = 1.f / s;
#pragma unroll
    for (int j = 0; j < 4; j++) {
        int c = t + j * 256;
        o[c] = (c < C_CLS) ? e[j] * inv : 0.f;
    }
}

// ---------------- launch ------------------------------------------------------
static float* symf(const void* p) { return (float*)p; }

extern "C" void kernel_launch(void* const* d_in, const int* in_sizes, int n_in,
                              void* d_out, int out_size) {
    const float* img    = (const float*)d_in[0];
    const float* attrs  = (const float*)d_in[1];
    const float* att_g  = (const float*)d_in[2];
    const float* att_h  = (const float*)d_in[3];
    const int*   labels = (const int*)d_in[4];
    const int*   tpl    = (const int*)d_in[5];
    float* out = (float*)d_out;
    int N = in_sizes[4];
    (void)n_in; (void)out_size;

    cudaFuncSetAttribute(mma_gemm_k, cudaFuncAttributeMaxDynamicSharedMemorySize, GSMEM);

    void *p_attr, *p_attrT, *p_p, *p_d, *p_A, *p_enc, *p_q, *p_protT, *p_hT, *p_gT;
    cudaGetSymbolAddress(&p_attr, g_attr);
    cudaGetSymbolAddress(&p_attrT, g_attrT);
    cudaGetSymbolAddress(&p_p, g_p);
    cudaGetSymbolAddress(&p_d, g_d);
    cudaGetSymbolAddress(&p_A, g_A);
    cudaGetSymbolAddress(&p_enc, g_enc);
    cudaGetSymbolAddress(&p_q, g_q);
    cudaGetSymbolAddress(&p_protT, g_protT);
    cudaGetSymbolAddress(&p_hT, g_hT);
    cudaGetSymbolAddress(&p_gT, g_gT);
    float *A_attr = symf(p_attr), *A_attrT = symf(p_attrT), *A_p = symf(p_p),
          *A_d = symf(p_d), *A_A = symf(p_A), *A_enc = symf(p_enc), *A_q = symf(p_q),
          *A_protT = symf(p_protT), *A_hT = symf(p_hT), *A_gT = symf(p_gT);

    // fork a side stream for the proto pipeline (captured via event edges)
    cudaStream_t s1;
    cudaStreamCreateWithFlags(&s1, cudaStreamNonBlocking);
    cudaEvent_t evF, evJ;
    cudaEventCreateWithFlags(&evF, cudaEventDisableTiming);
    cudaEventCreateWithFlags(&evJ, cudaEventDisableTiming);

    cudaEventRecord(evF, 0);
    cudaStreamWaitEvent(s1, evF, 0);

    // --- proto pipeline on side stream ---
    zero_counts_k<<<4, 256, 0, s1>>>();
    hist_k<<<25, 256, 0, s1>>>(labels, N);
    scan_k<<<1, 1024, 0, s1>>>();
    scatter_k<<<(N + 255) / 256, 256, 0, s1>>>(labels, N);
    class_mean_k<<<C_CLS, 128, 0, s1>>>(img);
    protT_k<<<dim3(AD / 32, CP / 32), dim3(32, 8), 0, s1>>>(tpl);
    cudaEventRecord(evJ, s1);

    // --- attribute chain on main stream ---
    pad_attr_k<<<CP, 128>>>(attrs);
    transpose_pad_k<<<dim3(AD / 32, CP / 32), dim3(32, 8)>>>(attrs, A_attrT, C_CLS, CP, AD);
    transpose_pad_k<<<dim3(HD / 32, AD / 32), dim3(32, 8)>>>(att_h, A_hT, AD, AD, HD);
    transpose_pad_k<<<dim3(HD / 32, AD / 32), dim3(32, 8)>>>(att_g, A_gT, AD, AD, HD);

    mma_gemm_k<<<dim3(HD / 64, CP / 128), 128, GSMEM>>>(A_attr, A_hT, A_p, HD, AD, CP);
    rownorm_k<<<CP, HD>>>(A_p);
    mma_gemm_k<<<dim3(CP / 64, CP / 128), 128, GSMEM>>>(A_p, A_p, A_d, CP, HD, CP);
    masked_softmax_k<<<CP, 256>>>(A_d, A_A);
    mma_gemm_k<<<dim3(AD / 64, CP / 128), 128, GSMEM>>>(A_A, A_attrT, A_enc, AD, CP, CP);
    mma_gemm_k<<<dim3(HD / 64, CP / 128), 128, GSMEM>>>(A_enc, A_gT, A_q, HD, AD, CP);
    rownorm_k<<<CP, HD>>>(A_q);
    mma_gemm_k<<<dim3(CP / 64, CP / 128), 128, GSMEM>>>(A_q, A_q, A_d, CP, HD, CP);
    masked_softmax_k<<<CP, 256>>>(A_d, A_A);

    // join proto pipeline, then final GEMM
    cudaStreamWaitEvent(0, evJ, 0);
    mma_gemm_k<<<dim3(AD / 64, CP / 128), 128, GSMEM>>>(A_A, A_protT, out, AD, CP, C_CLS);
}

// round 6
// speedup vs baseline: 2.5408x; 1.2982x over previous
#include <cuda_runtime.h>
#include <cstdint>
#include <math.h>

#define C_CLS 1000
#define CP    1024
#define AD    512
#define HD    256
#define NMAX  131072
#define KCH   32
#define SSTR  36
#define GSMEM ((2*128*SSTR + 2*64*SSTR) * 4)

// ---------------- scratch ----------------------------------------------------
__device__ float g_attr[CP * AD];      // padded attributes (GEMM A operand)
__device__ float g_p[CP * HD];
__device__ float g_G[CP * CP];         // gram matrix (both rounds)
__device__ float g_enc[CP * AD];
__device__ float g_q[CP * HD];
__device__ float g_mean[C_CLS * AD];
__device__ float g_prot[C_CLS * AD];   // gathered proto rows
__device__ float g_hT[HD * AD];
__device__ float g_gT[HD * AD];
__device__ float g_invn[CP];
__device__ float g_vals[CP * CP];      // packed softmax values
__device__ int   g_cols[CP * CP];      // packed softmax columns
__device__ int   g_nnz[CP];
__device__ int   g_counts[C_CLS];
__device__ int   g_offsets[C_CLS];
__device__ int   g_cursor[C_CLS];
__device__ int   g_sorted[NMAX];

// ---------------- helpers ----------------------------------------------------
__device__ __forceinline__ float warpSum(float v) {
#pragma unroll
    for (int o = 16; o; o >>= 1) v += __shfl_xor_sync(0xffffffffu, v, o);
    return v;
}
__device__ __forceinline__ float warpMax(float v) {
#pragma unroll
    for (int o = 16; o; o >>= 1) v = fmaxf(v, __shfl_xor_sync(0xffffffffu, v, o));
    return v;
}
__device__ __forceinline__ float blockSum(float v, float* sh) {
    int t = threadIdx.x, lane = t & 31, w = t >> 5, nw = blockDim.x >> 5;
    v = warpSum(v);
    if (!lane) sh[w] = v;
    __syncthreads();
    if (w == 0) {
        float x = (lane < nw) ? sh[lane] : 0.f;
        x = warpSum(x);
        if (!lane) sh[0] = x;
    }
    __syncthreads();
    float r = sh[0];
    __syncthreads();
    return r;
}
__device__ __forceinline__ float blockMax(float v, float* sh) {
    int t = threadIdx.x, lane = t & 31, w = t >> 5, nw = blockDim.x >> 5;
    v = warpMax(v);
    if (!lane) sh[w] = v;
    __syncthreads();
    if (w == 0) {
        float x = (lane < nw) ? sh[lane] : -1e30f;
        x = warpMax(x);
        if (!lane) sh[0] = x;
    }
    __syncthreads();
    float r = sh[0];
    __syncthreads();
    return r;
}
__device__ __forceinline__ uint32_t f2tf32(float x) {
    uint32_t r;
    asm("cvt.rna.tf32.f32 %0, %1;" : "=r"(r) : "f"(x));
    return r;
}
__device__ __forceinline__ void cp16(uint32_t dst, const void* src) {
    asm volatile("cp.async.ca.shared.global [%0], [%1], 16;" :: "r"(dst), "l"(src));
}
__device__ __forceinline__ void mma_tf32(float* c, const uint32_t* a, const uint32_t* b) {
    asm volatile(
        "mma.sync.aligned.m16n8k8.row.col.f32.tf32.tf32.f32 "
        "{%0,%1,%2,%3}, {%4,%5,%6,%7}, {%8,%9}, {%0,%1,%2,%3};"
        : "+f"(c[0]), "+f"(c[1]), "+f"(c[2]), "+f"(c[3])
        : "r"(a[0]), "r"(a[1]), "r"(a[2]), "r"(a[3]), "r"(b[0]), "r"(b[1]));
}

// ---------------- proto pipeline ---------------------------------------------
__global__ void zero_counts_k() {
    int i = blockIdx.x * blockDim.x + threadIdx.x;
    if (i < C_CLS) { g_counts[i] = 0; g_cursor[i] = 0; }
}
__global__ __launch_bounds__(256) void hist_k(const int* __restrict__ labels, int n) {
    __shared__ int h[C_CLS];
    for (int i = threadIdx.x; i < C_CLS; i += 256) h[i] = 0;
    __syncthreads();
    for (int i = blockIdx.x * blockDim.x + threadIdx.x; i < n; i += gridDim.x * blockDim.x)
        atomicAdd(&h[labels[i]], 1);
    __syncthreads();
    for (int i = threadIdx.x; i < C_CLS; i += 256)
        if (h[i]) atomicAdd(&g_counts[i], h[i]);
}
__global__ void scan_k() {
    __shared__ int s[1024];
    int t = threadIdx.x;
    int c = (t < C_CLS) ? g_counts[t] : 0;
    s[t] = c;
    __syncthreads();
    for (int off = 1; off < 1024; off <<= 1) {
        int v = (t >= off) ? s[t - off] : 0;
        __syncthreads();
        s[t] += v;
        __syncthreads();
    }
    if (t < C_CLS) g_offsets[t] = s[t] - c;
}
__global__ void scatter_k(const int* __restrict__ labels, int n) {
    int i = blockIdx.x * blockDim.x + threadIdx.x;
    if (i < n) {
        int l = labels[i];
        int pos = g_offsets[l] + atomicAdd(&g_cursor[l], 1);
        g_sorted[pos] = i;
    }
}
__global__ __launch_bounds__(128) void class_mean_k(const float* __restrict__ img) {
    int c = blockIdx.x;
    int t = threadIdx.x;
    int cnt = g_counts[c], off = g_offsets[c];
    __shared__ int idx[256];
    int lim = cnt < 256 ? cnt : 256;
    for (int j = t; j < lim; j += 128) idx[j] = g_sorted[off + j];
    __syncthreads();
    float4 acc = make_float4(0.f, 0.f, 0.f, 0.f);
    int j = 0;
    for (; j + 4 <= lim; j += 4) {
        float4 a = ((const float4*)(img + (size_t)idx[j] * AD))[t];
        float4 b = ((const float4*)(img + (size_t)idx[j + 1] * AD))[t];
        float4 d = ((const float4*)(img + (size_t)idx[j + 2] * AD))[t];
        float4 e = ((const float4*)(img + (size_t)idx[j + 3] * AD))[t];
        acc.x += a.x + b.x + d.x + e.x;
        acc.y += a.y + b.y + d.y + e.y;
        acc.z += a.z + b.z + d.z + e.z;
        acc.w += a.w + b.w + d.w + e.w;
    }
    for (; j < lim; j++) {
        float4 a = ((const float4*)(img + (size_t)idx[j] * AD))[t];
        acc.x += a.x; acc.y += a.y; acc.z += a.z; acc.w += a.w;
    }
    for (j = 256; j < cnt; j++) {
        float4 a = ((const float4*)(img + (size_t)g_sorted[off + j] * AD))[t];
        acc.x += a.x; acc.y += a.y; acc.z += a.z; acc.w += a.w;
    }
    float inv = cnt > 0 ? 1.f / (float)cnt : 0.f;
    ((float4*)(g_mean + (size_t)c * AD))[t] =
        make_float4(acc.x * inv, acc.y * inv, acc.z * inv, acc.w * inv);
}
__global__ void gather_prot_k(const int* __restrict__ tpl) {
    int i = blockIdx.x, t = threadIdx.x;
    ((float4*)(g_prot + (size_t)i * AD))[t] = ((const float4*)(g_mean + (size_t)tpl[i] * AD))[t];
}
__global__ void pad_attr_k(const float* __restrict__ attrs) {
    int i = blockIdx.x, t = threadIdx.x;
    float4 v = make_float4(0.f, 0.f, 0.f, 0.f);
    if (i < C_CLS) v = ((const float4*)(attrs + (size_t)i * AD))[t];
    ((float4*)(g_attr + (size_t)i * AD))[t] = v;
}

// ---------------- transpose (with zero padding of tail rows) -----------------
__global__ __launch_bounds__(256) void transpose_pad_k(const float* __restrict__ in,
                                                       float* __restrict__ out,
                                                       int R, int Rp, int Ccol) {
    __shared__ float t[32][33];
    int bx = blockIdx.x * 32, by = blockIdx.y * 32;
    int x = bx + threadIdx.x;
#pragma unroll
    for (int i = 0; i < 32; i += 8) {
        int y = by + threadIdx.y + i;
        t[threadIdx.y + i][threadIdx.x] = (y < R) ? in[(size_t)y * Ccol + x] : 0.f;
    }
    __syncthreads();
    x = by + threadIdx.x;
#pragma unroll
    for (int i = 0; i < 32; i += 8) {
        int y = bx + threadIdx.y + i;
        out[(size_t)y * Rp + x] = t[threadIdx.x][threadIdx.y + i];
    }
}

// ---------------- pipelined tf32 HMMA NT GEMM: C[M,N]=A[M,K]@B[N,K]^T --------
__global__ __launch_bounds__(128) void mma_gemm_k(const float* __restrict__ A,
                                                  const float* __restrict__ B,
                                                  float* __restrict__ Cc,
                                                  int N, int K, int mstore) {
    extern __shared__ float sm[];
    float* Asm = sm;
    float* Bsm = sm + 2 * 128 * SSTR;
    const int tid = threadIdx.x, wid = tid >> 5, lane = tid & 31;
    const int gid = lane >> 2, tig = lane & 3;
    const int m0 = blockIdx.y * 128, n0 = blockIdx.x * 64;
    const int wm = (wid & 1) * 64, wn = (wid >> 1) * 32;
    const uint32_t sbase = (uint32_t)__cvta_generic_to_shared(sm);

    float acc[4][4][4];
#pragma unroll
    for (int a = 0; a < 4; a++)
#pragma unroll
        for (int b = 0; b < 4; b++)
#pragma unroll
            for (int c = 0; c < 4; c++) acc[a][b][c] = 0.f;

    const int KC = K >> 5;

    auto loadc = [&](int kc, int buf) {
        const float* Ab = A + (size_t)m0 * K + kc * KCH;
        const float* Bb = B + (size_t)n0 * K + kc * KCH;
        uint32_t as0 = sbase + (uint32_t)(buf * 128 * SSTR) * 4u;
        uint32_t bs0 = sbase + (uint32_t)(2 * 128 * SSTR + buf * 64 * SSTR) * 4u;
#pragma unroll
        for (int i = 0; i < 8; i++) {
            int idx = tid + i * 128;
            int row = idx >> 3, kq = (idx & 7) * 4;
            cp16(as0 + (uint32_t)(row * SSTR + kq) * 4u, Ab + (size_t)row * K + kq);
        }
#pragma unroll
        for (int i = 0; i < 4; i++) {
            int idx = tid + i * 128;
            int row = idx >> 3, kq = (idx & 7) * 4;
            cp16(bs0 + (uint32_t)(row * SSTR + kq) * 4u, Bb + (size_t)row * K + kq);
        }
        asm volatile("cp.async.commit_group;" ::: "memory");
    };
    auto computec = [&](int buf) {
        const float* Ab = Asm + buf * 128 * SSTR;
        const float* Bb = Bsm + buf * 64 * SSTR;
#pragma unroll
        for (int ks = 0; ks < 4; ks++) {
            const int kb = ks * 8;
            uint32_t af[4][4], bf[4][2];
#pragma unroll
            for (int mf = 0; mf < 4; mf++) {
                int r = wm + mf * 16 + gid;
                af[mf][0] = f2tf32(Ab[r * SSTR + kb + tig]);
                af[mf][1] = f2tf32(Ab[(r + 8) * SSTR + kb + tig]);
                af[mf][2] = f2tf32(Ab[r * SSTR + kb + tig + 4]);
                af[mf][3] = f2tf32(Ab[(r + 8) * SSTR + kb + tig + 4]);
            }
#pragma unroll
            for (int nf = 0; nf < 4; nf++) {
                int r = wn + nf * 8 + gid;
                bf[nf][0] = f2tf32(Bb[r * SSTR + kb + tig]);
                bf[nf][1] = f2tf32(Bb[r * SSTR + kb + tig + 4]);
            }
#pragma unroll
            for (int mf = 0; mf < 4; mf++)
#pragma unroll
                for (int nf = 0; nf < 4; nf++) mma_tf32(acc[mf][nf], af[mf], bf[nf]);
        }
    };

    loadc(0, 0);
    for (int c = 0; c < KC; c++) {
        if (c + 1 < KC) {
            loadc(c + 1, (c + 1) & 1);
            asm volatile("cp.async.wait_group 1;" ::: "memory");
        } else {
            asm volatile("cp.async.wait_group 0;" ::: "memory");
        }
        __syncthreads();
        computec(c & 1);
        __syncthreads();
    }

#pragma unroll
    for (int mf = 0; mf < 4; mf++) {
#pragma unroll
        for (int nf = 0; nf < 4; nf++) {
            int col = n0 + wn + nf * 8 + tig * 2;
            int r0 = m0 + wm + mf * 16 + gid;
            if (r0 < mstore)
                *(float2*)(Cc + (size_t)r0 * N + col) =
                    make_float2(acc[mf][nf][0], acc[mf][nf][1]);
            int r1 = r0 + 8;
            if (r1 < mstore)
                *(float2*)(Cc + (size_t)r1 * N + col) =
                    make_float2(acc[mf][nf][2], acc[mf][nf][3]);
        }
    }
}

// ---------------- diag rsqrt -------------------------------------------------
__global__ void diag_k(const float* __restrict__ G) {
    int c = blockIdx.x * blockDim.x + threadIdx.x;
    if (c < CP)
        g_invn[c] = (c < C_CLS) ? rsqrtf(fmaxf(G[(size_t)c * CP + c], 1e-30f)) : 0.f;
}

// ---------------- masked softmax on gram -> packed sparse rows ---------------
__global__ __launch_bounds__(256) void softmax_sp_k(const float* __restrict__ G) {
    __shared__ float sh[32];
    __shared__ int cnt;
    int r = blockIdx.x;
    int t = threadIdx.x;
    if (r >= C_CLS) {
        if (t == 0) g_nnz[r] = 0;
        return;
    }
    const float* gr = G + (size_t)r * CP;
    float ir = g_invn[r];
    float v[4];
    float mx = -1e30f;
#pragma unroll
    for (int j = 0; j < 4; j++) {
        int c = t + j * 256;
        float x = (c < C_CLS) ? gr[c] * ir * g_invn[c] : -1e30f;
        v[j] = x;
        if (x > 0.5f) mx = fmaxf(mx, x);
    }
    mx = blockMax(mx, sh);
    float m10 = mx * 10.f;
    float e[4];
    float s = 0.f;
#pragma unroll
    for (int j = 0; j < 4; j++) {
        e[j] = (v[j] > 0.5f) ? expf(v[j] * 10.f - m10) : 0.f;
        s += e[j];
    }
    s = blockSum(s, sh);
    float inv = 1.f / s;
    if (t == 0) cnt = 0;
    __syncthreads();
#pragma unroll
    for (int j = 0; j < 4; j++) {
        if (e[j] > 0.f) {
            int slot = atomicAdd(&cnt, 1);
            g_cols[(size_t)r * CP + slot] = t + j * 256;
            g_vals[(size_t)r * CP + slot] = e[j] * inv;
        }
    }
    __syncthreads();
    if (t == 0) g_nnz[r] = cnt;
}

// ---------------- SpMM: C[r,:] = sum_i vals[r,i] * B[cols[r,i],:] ------------
__global__ __launch_bounds__(128) void spmm_k(const float* __restrict__ B,
                                              float* __restrict__ Cc, int mstore) {
    int r = blockIdx.x;
    int t = threadIdx.x;                 // float4 column
    float4 acc = make_float4(0.f, 0.f, 0.f, 0.f);
    int n = g_nnz[r];
    const int*   cols = g_cols + (size_t)r * CP;
    const float* vals = g_vals + (size_t)r * CP;
    for (int i = 0; i < n; i++) {
        int c = cols[i];
        float v = vals[i];
        float4 b = ((const float4*)(B + (size_t)c * AD))[t];
        acc.x += v * b.x; acc.y += v * b.y; acc.z += v * b.z; acc.w += v * b.w;
    }
    if (r < mstore) ((float4*)(Cc + (size_t)r * AD))[t] = acc;
}

// ---------------- launch ------------------------------------------------------
static float* symf(const void* p) { return (float*)p; }

extern "C" void kernel_launch(void* const* d_in, const int* in_sizes, int n_in,
                              void* d_out, int out_size) {
    const float* img    = (const float*)d_in[0];
    const float* attrs  = (const float*)d_in[1];
    const float* att_g  = (const float*)d_in[2];
    const float* att_h  = (const float*)d_in[3];
    const int*   labels = (const int*)d_in[4];
    const int*   tpl    = (const int*)d_in[5];
    float* out = (float*)d_out;
    int N = in_sizes[4];
    (void)n_in; (void)out_size;

    cudaFuncSetAttribute(mma_gemm_k, cudaFuncAttributeMaxDynamicSharedMemorySize, GSMEM);

    void *p_attr, *p_p, *p_G, *p_enc, *p_q, *p_prot, *p_hT, *p_gT;
    cudaGetSymbolAddress(&p_attr, g_attr);
    cudaGetSymbolAddress(&p_p, g_p);
    cudaGetSymbolAddress(&p_G, g_G);
    cudaGetSymbolAddress(&p_enc, g_enc);
    cudaGetSymbolAddress(&p_q, g_q);
    cudaGetSymbolAddress(&p_prot, g_prot);
    cudaGetSymbolAddress(&p_hT, g_hT);
    cudaGetSymbolAddress(&p_gT, g_gT);
    float *A_attr = symf(p_attr), *A_p = symf(p_p), *A_G = symf(p_G),
          *A_enc = symf(p_enc), *A_q = symf(p_q), *A_prot = symf(p_prot),
          *A_hT = symf(p_hT), *A_gT = symf(p_gT);

    cudaStream_t s1;
    cudaStreamCreateWithFlags(&s1, cudaStreamNonBlocking);
    cudaEvent_t evF, evG, evJ;
    cudaEventCreateWithFlags(&evF, cudaEventDisableTiming);
    cudaEventCreateWithFlags(&evG, cudaEventDisableTiming);
    cudaEventCreateWithFlags(&evJ, cudaEventDisableTiming);

    cudaEventRecord(evF, 0);
    cudaStreamWaitEvent(s1, evF, 0);

    // --- side stream: gT transpose + proto pipeline ---
    transpose_pad_k<<<dim3(HD / 32, AD / 32), dim3(32, 8), 0, s1>>>(att_g, A_gT, AD, AD, HD);
    cudaEventRecord(evG, s1);
    zero_counts_k<<<4, 256, 0, s1>>>();
    hist_k<<<25, 256, 0, s1>>>(labels, N);
    scan_k<<<1, 1024, 0, s1>>>();
    scatter_k<<<(N + 255) / 256, 256, 0, s1>>>(labels, N);
    class_mean_k<<<C_CLS, 128, 0, s1>>>(img);
    gather_prot_k<<<C_CLS, 128, 0, s1>>>(tpl);
    cudaEventRecord(evJ, s1);

    // --- main stream: attribute chain ---
    pad_attr_k<<<CP, 128>>>(attrs);
    transpose_pad_k<<<dim3(HD / 32, AD / 32), dim3(32, 8)>>>(att_h, A_hT, AD, AD, HD);

    // p = attr_pad @ att_h : [CP,HD], K=AD
    mma_gemm_k<<<dim3(HD / 64, CP / 128), 128, GSMEM>>>(A_attr, A_hT, A_p, HD, AD, CP);
    // G = p @ p^T : [CP,CP], K=HD
    mma_gemm_k<<<dim3(CP / 64, CP / 128), 128, GSMEM>>>(A_p, A_p, A_G, CP, HD, CP);
    diag_k<<<CP / 256, 256>>>(A_G);
    softmax_sp_k<<<CP, 256>>>(A_G);
    // enc = attention @ attrs (sparse)
    spmm_k<<<CP, 128>>>(attrs, A_enc, CP);
    // q = enc @ att_g : [CP,HD], K=AD
    cudaStreamWaitEvent(0, evG, 0);
    mma_gemm_k<<<dim3(HD / 64, CP / 128), 128, GSMEM>>>(A_enc, A_gT, A_q, HD, AD, CP);
    // G2 = q @ q^T
    mma_gemm_k<<<dim3(CP / 64, CP / 128), 128, GSMEM>>>(A_q, A_q, A_G, CP, HD, CP);
    diag_k<<<CP / 256, 256>>>(A_G);
    softmax_sp_k<<<CP, 256>>>(A_G);
    // out = attention2 @ protos (sparse), rows < C_CLS
    cudaStreamWaitEvent(0, evJ, 0);
    spmm_k<<<CP, 128>>>(A_prot, out, C_CLS);
}

// round 7
// speedup vs baseline: 3.1330x; 1.2330x over previous
#include <cuda_runtime.h>
#include <cstdint>
#include <math.h>

#define C_CLS 1000
#define CP    1024
#define AD    512
#define HD    256
#define NMAX  131072
#define KCH   32
#define SSTR  36
#define GSMEM ((2*128*SSTR + 2*64*SSTR) * 4)

// ---------------- scratch ----------------------------------------------------
__device__ float g_attr[CP * AD];
__device__ float g_p[CP * HD];
__device__ float g_G[CP * CP];
__device__ float g_enc[CP * AD];
__device__ float g_q[CP * HD];
__device__ float g_mean[C_CLS * AD];
__device__ float g_prot[C_CLS * AD];
__device__ float g_hT[HD * AD];
__device__ float g_gT[HD * AD];
__device__ float g_invn[CP];
__device__ float g_part[4 * CP * HD];  // split-K partials
__device__ float g_vals[CP * CP];
__device__ int   g_cols[CP * CP];
__device__ int   g_nnz[CP];
__device__ int   g_counts[C_CLS];
__device__ int   g_offsets[C_CLS];
__device__ int   g_cursor[C_CLS];
__device__ int   g_sorted[NMAX];

// ---------------- helpers ----------------------------------------------------
__device__ __forceinline__ float warpSum(float v) {
#pragma unroll
    for (int o = 16; o; o >>= 1) v += __shfl_xor_sync(0xffffffffu, v, o);
    return v;
}
__device__ __forceinline__ float warpMax(float v) {
#pragma unroll
    for (int o = 16; o; o >>= 1) v = fmaxf(v, __shfl_xor_sync(0xffffffffu, v, o));
    return v;
}
__device__ __forceinline__ float blockSum(float v, float* sh) {
    int t = threadIdx.x, lane = t & 31, w = t >> 5, nw = blockDim.x >> 5;
    v = warpSum(v);
    if (!lane) sh[w] = v;
    __syncthreads();
    if (w == 0) {
        float x = (lane < nw) ? sh[lane] : 0.f;
        x = warpSum(x);
        if (!lane) sh[0] = x;
    }
    __syncthreads();
    float r = sh[0];
    __syncthreads();
    return r;
}
__device__ __forceinline__ float blockMax(float v, float* sh) {
    int t = threadIdx.x, lane = t & 31, w = t >> 5, nw = blockDim.x >> 5;
    v = warpMax(v);
    if (!lane) sh[w] = v;
    __syncthreads();
    if (w == 0) {
        float x = (lane < nw) ? sh[lane] : -1e30f;
        x = warpMax(x);
        if (!lane) sh[0] = x;
    }
    __syncthreads();
    float r = sh[0];
    __syncthreads();
    return r;
}
__device__ __forceinline__ uint32_t f2tf32(float x) {
    uint32_t r;
    asm("cvt.rna.tf32.f32 %0, %1;" : "=r"(r) : "f"(x));
    return r;
}
__device__ __forceinline__ void cp16(uint32_t dst, const void* src) {
    asm volatile("cp.async.ca.shared.global [%0], [%1], 16;" :: "r"(dst), "l"(src));
}
__device__ __forceinline__ void mma_tf32(float* c, const uint32_t* a, const uint32_t* b) {
    asm volatile(
        "mma.sync.aligned.m16n8k8.row.col.f32.tf32.tf32.f32 "
        "{%0,%1,%2,%3}, {%4,%5,%6,%7}, {%8,%9}, {%0,%1,%2,%3};"
        : "+f"(c[0]), "+f"(c[1]), "+f"(c[2]), "+f"(c[3])
        : "r"(a[0]), "r"(a[1]), "r"(a[2]), "r"(a[3]), "r"(b[0]), "r"(b[1]));
}

// ---------------- proto pipeline ---------------------------------------------
__global__ __launch_bounds__(256) void hist_k(const int* __restrict__ labels, int n) {
    __shared__ int h[C_CLS];
    for (int i = threadIdx.x; i < C_CLS; i += 256) h[i] = 0;
    __syncthreads();
    for (int i = blockIdx.x * blockDim.x + threadIdx.x; i < n; i += gridDim.x * blockDim.x)
        atomicAdd(&h[labels[i]], 1);
    __syncthreads();
    for (int i = threadIdx.x; i < C_CLS; i += 256)
        if (h[i]) atomicAdd(&g_counts[i], h[i]);
}
__global__ void scan_warp_k() {   // 1 warp, exclusive prefix over 1000 counts
    int lane = threadIdx.x;
    int base = lane * 32;
    int loc[32];
    int s = 0;
#pragma unroll
    for (int j = 0; j < 32; j++) {
        int idx = base + j;
        int c = (idx < C_CLS) ? g_counts[idx] : 0;
        loc[j] = s;
        s += c;
    }
    int inc = s;
#pragma unroll
    for (int o = 1; o < 32; o <<= 1) {
        int nv = __shfl_up_sync(0xffffffffu, inc, o);
        if (lane >= o) inc += nv;
    }
    int excl = inc - s;
#pragma unroll
    for (int j = 0; j < 32; j++) {
        int idx = base + j;
        if (idx < C_CLS) g_offsets[idx] = excl + loc[j];
    }
}
__global__ void scatter_k(const int* __restrict__ labels, int n) {
    int i = blockIdx.x * blockDim.x + threadIdx.x;
    if (i < n) {
        int l = labels[i];
        int pos = g_offsets[l] + atomicAdd(&g_cursor[l], 1);
        g_sorted[pos] = i;
    }
}
__global__ __launch_bounds__(128) void class_mean_k(const float* __restrict__ img) {
    int c = blockIdx.x;
    int t = threadIdx.x;
    int cnt = g_counts[c], off = g_offsets[c];
    __shared__ int idx[256];
    int lim = cnt < 256 ? cnt : 256;
    for (int j = t; j < lim; j += 128) idx[j] = g_sorted[off + j];
    __syncthreads();
    float4 acc = make_float4(0.f, 0.f, 0.f, 0.f);
    int j = 0;
    for (; j + 4 <= lim; j += 4) {
        float4 a = ((const float4*)(img + (size_t)idx[j] * AD))[t];
        float4 b = ((const float4*)(img + (size_t)idx[j + 1] * AD))[t];
        float4 d = ((const float4*)(img + (size_t)idx[j + 2] * AD))[t];
        float4 e = ((const float4*)(img + (size_t)idx[j + 3] * AD))[t];
        acc.x += a.x + b.x + d.x + e.x;
        acc.y += a.y + b.y + d.y + e.y;
        acc.z += a.z + b.z + d.z + e.z;
        acc.w += a.w + b.w + d.w + e.w;
    }
    for (; j < lim; j++) {
        float4 a = ((const float4*)(img + (size_t)idx[j] * AD))[t];
        acc.x += a.x; acc.y += a.y; acc.z += a.z; acc.w += a.w;
    }
    for (j = 256; j < cnt; j++) {
        float4 a = ((const float4*)(img + (size_t)g_sorted[off + j] * AD))[t];
        acc.x += a.x; acc.y += a.y; acc.z += a.z; acc.w += a.w;
    }
    float inv = cnt > 0 ? 1.f / (float)cnt : 0.f;
    ((float4*)(g_mean + (size_t)c * AD))[t] =
        make_float4(acc.x * inv, acc.y * inv, acc.z * inv, acc.w * inv);
}
__global__ void gather_prot_k(const int* __restrict__ tpl) {
    int i = blockIdx.x, t = threadIdx.x;
    ((float4*)(g_prot + (size_t)i * AD))[t] = ((const float4*)(g_mean + (size_t)tpl[i] * AD))[t];
}
__global__ void pad_attr_k(const float* __restrict__ attrs) {
    int i = blockIdx.x, t = threadIdx.x;
    float4 v = make_float4(0.f, 0.f, 0.f, 0.f);
    if (i < C_CLS) v = ((const float4*)(attrs + (size_t)i * AD))[t];
    ((float4*)(g_attr + (size_t)i * AD))[t] = v;
}

// ---------------- transpose (with zero padding of tail rows) -----------------
__global__ __launch_bounds__(256) void transpose_pad_k(const float* __restrict__ in,
                                                       float* __restrict__ out,
                                                       int R, int Rp, int Ccol) {
    __shared__ float t[32][33];
    int bx = blockIdx.x * 32, by = blockIdx.y * 32;
    int x = bx + threadIdx.x;
#pragma unroll
    for (int i = 0; i < 32; i += 8) {
        int y = by + threadIdx.y + i;
        t[threadIdx.y + i][threadIdx.x] = (y < R) ? in[(size_t)y * Ccol + x] : 0.f;
    }
    __syncthreads();
    x = by + threadIdx.x;
#pragma unroll
    for (int i = 0; i < 32; i += 8) {
        int y = bx + threadIdx.y + i;
        out[(size_t)y * Rp + x] = t[threadIdx.x][threadIdx.y + i];
    }
}

// ------ pipelined tf32 HMMA NT GEMM with split-K & fused diag-rsqrt ---------
// C[M,N]=A[M,K]@B[N,K]^T ; blockIdx.z = K-slice (dst += z*CP*N)
__global__ __launch_bounds__(128) void mma_gemm_k(const float* __restrict__ A,
                                                  const float* __restrict__ B,
                                                  float* __restrict__ Cc,
                                                  int N, int K, int nch,
                                                  int mstore, int diagflag) {
    extern __shared__ float sm[];
    float* Asm = sm;
    float* Bsm = sm + 2 * 128 * SSTR;
    const int tid = threadIdx.x, wid = tid >> 5, lane = tid & 31;
    const int gid = lane >> 2, tig = lane & 3;
    const int m0 = blockIdx.y * 128, n0 = blockIdx.x * 64;
    const int wm = (wid & 1) * 64, wn = (wid >> 1) * 32;
    const int kbase = blockIdx.z * nch * KCH;
    float* dst = Cc + (size_t)blockIdx.z * CP * N;
    const uint32_t sbase = (uint32_t)__cvta_generic_to_shared(sm);

    float acc[4][4][4];
#pragma unroll
    for (int a = 0; a < 4; a++)
#pragma unroll
        for (int b = 0; b < 4; b++)
#pragma unroll
            for (int c = 0; c < 4; c++) acc[a][b][c] = 0.f;

    auto loadc = [&](int kc, int buf) {
        const float* Ab = A + (size_t)m0 * K + kbase + kc * KCH;
        const float* Bb = B + (size_t)n0 * K + kbase + kc * KCH;
        uint32_t as0 = sbase + (uint32_t)(buf * 128 * SSTR) * 4u;
        uint32_t bs0 = sbase + (uint32_t)(2 * 128 * SSTR + buf * 64 * SSTR) * 4u;
#pragma unroll
        for (int i = 0; i < 8; i++) {
            int idx = tid + i * 128;
            int row = idx >> 3, kq = (idx & 7) * 4;
            cp16(as0 + (uint32_t)(row * SSTR + kq) * 4u, Ab + (size_t)row * K + kq);
        }
#pragma unroll
        for (int i = 0; i < 4; i++) {
            int idx = tid + i * 128;
            int row = idx >> 3, kq = (idx & 7) * 4;
            cp16(bs0 + (uint32_t)(row * SSTR + kq) * 4u, Bb + (size_t)row * K + kq);
        }
        asm volatile("cp.async.commit_group;" ::: "memory");
    };
    auto computec = [&](int buf) {
        const float* Ab = Asm + buf * 128 * SSTR;
        const float* Bb = Bsm + buf * 64 * SSTR;
#pragma unroll
        for (int ks = 0; ks < 4; ks++) {
            const int kb = ks * 8;
            uint32_t af[4][4], bf[4][2];
#pragma unroll
            for (int mf = 0; mf < 4; mf++) {
                int r = wm + mf * 16 + gid;
                af[mf][0] = f2tf32(Ab[r * SSTR + kb + tig]);
                af[mf][1] = f2tf32(Ab[(r + 8) * SSTR + kb + tig]);
                af[mf][2] = f2tf32(Ab[r * SSTR + kb + tig + 4]);
                af[mf][3] = f2tf32(Ab[(r + 8) * SSTR + kb + tig + 4]);
            }
#pragma unroll
            for (int nf = 0; nf < 4; nf++) {
                int r = wn + nf * 8 + gid;
                bf[nf][0] = f2tf32(Bb[r * SSTR + kb + tig]);
                bf[nf][1] = f2tf32(Bb[r * SSTR + kb + tig + 4]);
            }
#pragma unroll
            for (int mf = 0; mf < 4; mf++)
#pragma unroll
                for (int nf = 0; nf < 4; nf++) mma_tf32(acc[mf][nf], af[mf], bf[nf]);
        }
    };

    loadc(0, 0);
    for (int c = 0; c < nch; c++) {
        if (c + 1 < nch) {
            loadc(c + 1, (c + 1) & 1);
            asm volatile("cp.async.wait_group 1;" ::: "memory");
        } else {
            asm volatile("cp.async.wait_group 0;" ::: "memory");
        }
        __syncthreads();
        computec(c & 1);
        __syncthreads();
    }

#pragma unroll
    for (int mf = 0; mf < 4; mf++) {
#pragma unroll
        for (int nf = 0; nf < 4; nf++) {
            int col = n0 + wn + nf * 8 + tig * 2;
            int r0 = m0 + wm + mf * 16 + gid;
            if (r0 < mstore) {
                *(float2*)(dst + (size_t)r0 * N + col) =
                    make_float2(acc[mf][nf][0], acc[mf][nf][1]);
                if (diagflag) {
                    if (r0 == col)     g_invn[r0] = rsqrtf(fmaxf(acc[mf][nf][0], 1e-30f));
                    if (r0 == col + 1) g_invn[r0] = rsqrtf(fmaxf(acc[mf][nf][1], 1e-30f));
                }
            }
            int r1 = r0 + 8;
            if (r1 < mstore) {
                *(float2*)(dst + (size_t)r1 * N + col) =
                    make_float2(acc[mf][nf][2], acc[mf][nf][3]);
                if (diagflag) {
                    if (r1 == col)     g_invn[r1] = rsqrtf(fmaxf(acc[mf][nf][2], 1e-30f));
                    if (r1 == col + 1) g_invn[r1] = rsqrtf(fmaxf(acc[mf][nf][3], 1e-30f));
                }
            }
        }
    }
}

// ---------------- split-K reduce: out = sum of 4 partial slices --------------
__global__ __launch_bounds__(256) void reduce4_k(float* __restrict__ out) {
    int i = blockIdx.x * blockDim.x + threadIdx.x;     // float4 index
    const int n4 = CP * HD / 4;
    if (i < n4) {
        const float4* p = (const float4*)g_part;
        float4 a = p[i], b = p[i + n4], c = p[i + 2 * n4], d = p[i + 3 * n4];
        ((float4*)out)[i] = make_float4(a.x + b.x + c.x + d.x, a.y + b.y + c.y + d.y,
                                        a.z + b.z + c.z + d.z, a.w + b.w + c.w + d.w);
    }
}

// ---------------- masked softmax on gram -> packed sparse rows ---------------
__global__ __launch_bounds__(256) void softmax_sp_k(const float* __restrict__ G) {
    __shared__ float sh[32];
    __shared__ int cnt;
    int r = blockIdx.x;
    int t = threadIdx.x;
    if (r >= C_CLS) {
        if (t == 0) g_nnz[r] = 0;
        return;
    }
    const float* gr = G + (size_t)r * CP;
    float ir = g_invn[r];
    float v[4];
    float mx = -1e30f;
#pragma unroll
    for (int j = 0; j < 4; j++) {
        int c = t + j * 256;
        float x = (c < C_CLS) ? gr[c] * ir * g_invn[c] : -1e30f;
        v[j] = x;
        if (x > 0.5f) mx = fmaxf(mx, x);
    }
    mx = blockMax(mx, sh);
    float m10 = mx * 10.f;
    float e[4];
    float s = 0.f;
#pragma unroll
    for (int j = 0; j < 4; j++) {
        e[j] = (v[j] > 0.5f) ? expf(v[j] * 10.f - m10) : 0.f;
        s += e[j];
    }
    s = blockSum(s, sh);
    float inv = 1.f / s;
    if (t == 0) cnt = 0;
    __syncthreads();
#pragma unroll
    for (int j = 0; j < 4; j++) {
        if (e[j] > 0.f) {
            int slot = atomicAdd(&cnt, 1);
            g_cols[(size_t)r * CP + slot] = t + j * 256;
            g_vals[(size_t)r * CP + slot] = e[j] * inv;
        }
    }
    __syncthreads();
    if (t == 0) g_nnz[r] = cnt;
}

// ---------------- SpMM -------------------------------------------------------
__global__ __launch_bounds__(128) void spmm_k(const float* __restrict__ B,
                                              float* __restrict__ Cc, int mstore) {
    int r = blockIdx.x;
    int t = threadIdx.x;
    float4 acc = make_float4(0.f, 0.f, 0.f, 0.f);
    int n = g_nnz[r];
    const int*   cols = g_cols + (size_t)r * CP;
    const float* vals = g_vals + (size_t)r * CP;
    for (int i = 0; i < n; i++) {
        int c = cols[i];
        float v = vals[i];
        float4 b = ((const float4*)(B + (size_t)c * AD))[t];
        acc.x += v * b.x; acc.y += v * b.y; acc.z += v * b.z; acc.w += v * b.w;
    }
    if (r < mstore) ((float4*)(Cc + (size_t)r * AD))[t] = acc;
}

// ---------------- launch ------------------------------------------------------
static float* symf(const void* p) { return (float*)p; }

extern "C" void kernel_launch(void* const* d_in, const int* in_sizes, int n_in,
                              void* d_out, int out_size) {
    const float* img    = (const float*)d_in[0];
    const float* attrs  = (const float*)d_in[1];
    const float* att_g  = (const float*)d_in[2];
    const float* att_h  = (const float*)d_in[3];
    const int*   labels = (const int*)d_in[4];
    const int*   tpl    = (const int*)d_in[5];
    float* out = (float*)d_out;
    int N = in_sizes[4];
    (void)n_in; (void)out_size;

    cudaFuncSetAttribute(mma_gemm_k, cudaFuncAttributeMaxDynamicSharedMemorySize, GSMEM);

    void *p_attr, *p_p, *p_G, *p_enc, *p_q, *p_prot, *p_hT, *p_gT, *p_part,
         *p_counts, *p_cursor;
    cudaGetSymbolAddress(&p_attr, g_attr);
    cudaGetSymbolAddress(&p_p, g_p);
    cudaGetSymbolAddress(&p_G, g_G);
    cudaGetSymbolAddress(&p_enc, g_enc);
    cudaGetSymbolAddress(&p_q, g_q);
    cudaGetSymbolAddress(&p_prot, g_prot);
    cudaGetSymbolAddress(&p_hT, g_hT);
    cudaGetSymbolAddress(&p_gT, g_gT);
    cudaGetSymbolAddress(&p_part, g_part);
    cudaGetSymbolAddress(&p_counts, g_counts);
    cudaGetSymbolAddress(&p_cursor, g_cursor);
    float *A_attr = symf(p_attr), *A_p = symf(p_p), *A_G = symf(p_G),
          *A_enc = symf(p_enc), *A_q = symf(p_q), *A_prot = symf(p_prot),
          *A_hT = symf(p_hT), *A_gT = symf(p_gT), *A_part = symf(p_part);

    cudaStream_t s1;
    cudaStreamCreateWithFlags(&s1, cudaStreamNonBlocking);
    cudaEvent_t evF, evG, evJ;
    cudaEventCreateWithFlags(&evF, cudaEventDisableTiming);
    cudaEventCreateWithFlags(&evG, cudaEventDisableTiming);
    cudaEventCreateWithFlags(&evJ, cudaEventDisableTiming);

    cudaEventRecord(evF, 0);
    cudaStreamWaitEvent(s1, evF, 0);

    // --- side stream: gT transpose + proto pipeline ---
    transpose_pad_k<<<dim3(HD / 32, AD / 32), dim3(32, 8), 0, s1>>>(att_g, A_gT, AD, AD, HD);
    cudaEventRecord(evG, s1);
    cudaMemsetAsync(p_counts, 0, C_CLS * sizeof(int), s1);
    cudaMemsetAsync(p_cursor, 0, C_CLS * sizeof(int), s1);
    hist_k<<<25, 256, 0, s1>>>(labels, N);
    scan_warp_k<<<1, 32, 0, s1>>>();
    scatter_k<<<(N + 255) / 256, 256, 0, s1>>>(labels, N);
    class_mean_k<<<C_CLS, 128, 0, s1>>>(img);
    gather_prot_k<<<C_CLS, 128, 0, s1>>>(tpl);
    cudaEventRecord(evJ, s1);

    // --- main stream: attribute chain ---
    pad_attr_k<<<CP, 128>>>(attrs);
    transpose_pad_k<<<dim3(HD / 32, AD / 32), dim3(32, 8)>>>(att_h, A_hT, AD, AD, HD);

    // p = attr_pad @ att_h  (split-K x4)
    mma_gemm_k<<<dim3(HD / 64, CP / 128, 4), 128, GSMEM>>>(A_attr, A_hT, A_part, HD, AD, 4, CP, 0);
    reduce4_k<<<CP * HD / 4 / 256, 256>>>(A_p);
    // G1 = p @ p^T (fused diag rsqrt)
    mma_gemm_k<<<dim3(CP / 64, CP / 128, 1), 128, GSMEM>>>(A_p, A_p, A_G, CP, HD, 8, CP, 1);
    softmax_sp_k<<<CP, 256>>>(A_G);
    spmm_k<<<CP, 128>>>(attrs, A_enc, CP);
    // q = enc @ att_g (split-K x4)
    cudaStreamWaitEvent(0, evG, 0);
    mma_gemm_k<<<dim3(HD / 64, CP / 128, 4), 128, GSMEM>>>(A_enc, A_gT, A_part, HD, AD, 4, CP, 0);
    reduce4_k<<<CP * HD / 4 / 256, 256>>>(A_q);
    // G2 = q @ q^T
    mma_gemm_k<<<dim3(CP / 64, CP / 128, 1), 128, GSMEM>>>(A_q, A_q, A_G, CP, HD, 8, CP, 1);
    softmax_sp_k<<<CP, 256>>>(A_G);
    // out = attention2 @ protos
    cudaStreamWaitEvent(0, evJ, 0);
    spmm_k<<<CP, 128>>>(A_prot, out, C_CLS);
}

// round 8
// speedup vs baseline: 3.5942x; 1.1472x over previous
#include <cuda_runtime.h>
#include <cstdint>
#include <math.h>

#define C_CLS 1000
#define CP    1024
#define AD    512
#define HD    256
#define NMAX  131072
#define KCH   32
#define SSTR  36
#define GSMEM ((2*128*SSTR + 2*64*SSTR) * 4)

// ---------------- scratch ----------------------------------------------------
__device__ float g_attr[CP * AD];
__device__ float g_p[CP * HD];
__device__ float g_G[CP * CP];
__device__ float g_enc[CP * AD];
__device__ float g_q[CP * HD];
__device__ float g_mean[C_CLS * AD];
__device__ float g_prot[C_CLS * AD];
__device__ float g_hT[HD * AD];
__device__ float g_gT[HD * AD];
__device__ float g_invn[CP];
__device__ float g_part[4 * CP * HD];
__device__ int   g_counts[C_CLS];
__device__ int   g_offsets[C_CLS];
__device__ int   g_cursor[C_CLS];
__device__ int   g_sorted[NMAX];

// ---------------- helpers ----------------------------------------------------
__device__ __forceinline__ float warpSum(float v) {
#pragma unroll
    for (int o = 16; o; o >>= 1) v += __shfl_xor_sync(0xffffffffu, v, o);
    return v;
}
__device__ __forceinline__ float warpMax(float v) {
#pragma unroll
    for (int o = 16; o; o >>= 1) v = fmaxf(v, __shfl_xor_sync(0xffffffffu, v, o));
    return v;
}
__device__ __forceinline__ float blockSum(float v, float* sh) {
    int t = threadIdx.x, lane = t & 31, w = t >> 5, nw = blockDim.x >> 5;
    v = warpSum(v);
    if (!lane) sh[w] = v;
    __syncthreads();
    if (w == 0) {
        float x = (lane < nw) ? sh[lane] : 0.f;
        x = warpSum(x);
        if (!lane) sh[0] = x;
    }
    __syncthreads();
    float r = sh[0];
    __syncthreads();
    return r;
}
__device__ __forceinline__ float blockMax(float v, float* sh) {
    int t = threadIdx.x, lane = t & 31, w = t >> 5, nw = blockDim.x >> 5;
    v = warpMax(v);
    if (!lane) sh[w] = v;
    __syncthreads();
    if (w == 0) {
        float x = (lane < nw) ? sh[lane] : -1e30f;
        x = warpMax(x);
        if (!lane) sh[0] = x;
    }
    __syncthreads();
    float r = sh[0];
    __syncthreads();
    return r;
}
__device__ __forceinline__ void cp16(uint32_t dst, const void* src) {
    asm volatile("cp.async.ca.shared.global [%0], [%1], 16;" :: "r"(dst), "l"(src));
}
__device__ __forceinline__ void mma_tf32(float* c, const uint32_t* a, const uint32_t* b) {
    asm volatile(
        "mma.sync.aligned.m16n8k8.row.col.f32.tf32.tf32.f32 "
        "{%0,%1,%2,%3}, {%4,%5,%6,%7}, {%8,%9}, {%0,%1,%2,%3};"
        : "+f"(c[0]), "+f"(c[1]), "+f"(c[2]), "+f"(c[3])
        : "r"(a[0]), "r"(a[1]), "r"(a[2]), "r"(a[3]), "r"(b[0]), "r"(b[1]));
}

// ---------------- proto pipeline ---------------------------------------------
__global__ __launch_bounds__(256) void hist_k(const int* __restrict__ labels, int n) {
    __shared__ int h[C_CLS];
    for (int i = threadIdx.x; i < C_CLS; i += 256) h[i] = 0;
    __syncthreads();
    for (int i = blockIdx.x * blockDim.x + threadIdx.x; i < n; i += gridDim.x * blockDim.x)
        atomicAdd(&h[labels[i]], 1);
    __syncthreads();
    for (int i = threadIdx.x; i < C_CLS; i += 256)
        if (h[i]) atomicAdd(&g_counts[i], h[i]);
}
__global__ void scan_warp_k() {
    int lane = threadIdx.x;
    int base = lane * 32;
    int loc[32];
    int s = 0;
#pragma unroll
    for (int j = 0; j < 32; j++) {
        int idx = base + j;
        int c = (idx < C_CLS) ? g_counts[idx] : 0;
        loc[j] = s;
        s += c;
    }
    int inc = s;
#pragma unroll
    for (int o = 1; o < 32; o <<= 1) {
        int nv = __shfl_up_sync(0xffffffffu, inc, o);
        if (lane >= o) inc += nv;
    }
    int excl = inc - s;
#pragma unroll
    for (int j = 0; j < 32; j++) {
        int idx = base + j;
        if (idx < C_CLS) g_offsets[idx] = excl + loc[j];
    }
}
__global__ void scatter_k(const int* __restrict__ labels, int n) {
    int i = blockIdx.x * blockDim.x + threadIdx.x;
    if (i < n) {
        int l = labels[i];
        int pos = g_offsets[l] + atomicAdd(&g_cursor[l], 1);
        g_sorted[pos] = i;
    }
}
__global__ __launch_bounds__(128) void class_mean_k(const float* __restrict__ img) {
    int c = blockIdx.x;
    int t = threadIdx.x;
    int cnt = g_counts[c], off = g_offsets[c];
    __shared__ int idx[256];
    int lim = cnt < 256 ? cnt : 256;
    for (int j = t; j < lim; j += 128) idx[j] = g_sorted[off + j];
    __syncthreads();
    float4 acc = make_float4(0.f, 0.f, 0.f, 0.f);
    int j = 0;
    for (; j + 4 <= lim; j += 4) {
        float4 a = ((const float4*)(img + (size_t)idx[j] * AD))[t];
        float4 b = ((const float4*)(img + (size_t)idx[j + 1] * AD))[t];
        float4 d = ((const float4*)(img + (size_t)idx[j + 2] * AD))[t];
        float4 e = ((const float4*)(img + (size_t)idx[j + 3] * AD))[t];
        acc.x += a.x + b.x + d.x + e.x;
        acc.y += a.y + b.y + d.y + e.y;
        acc.z += a.z + b.z + d.z + e.z;
        acc.w += a.w + b.w + d.w + e.w;
    }
    for (; j < lim; j++) {
        float4 a = ((const float4*)(img + (size_t)idx[j] * AD))[t];
        acc.x += a.x; acc.y += a.y; acc.z += a.z; acc.w += a.w;
    }
    for (j = 256; j < cnt; j++) {
        float4 a = ((const float4*)(img + (size_t)g_sorted[off + j] * AD))[t];
        acc.x += a.x; acc.y += a.y; acc.z += a.z; acc.w += a.w;
    }
    float inv = cnt > 0 ? 1.f / (float)cnt : 0.f;
    ((float4*)(g_mean + (size_t)c * AD))[t] =
        make_float4(acc.x * inv, acc.y * inv, acc.z * inv, acc.w * inv);
}
__global__ void gather_prot_k(const int* __restrict__ tpl) {
    int i = blockIdx.x, t = threadIdx.x;
    ((float4*)(g_prot + (size_t)i * AD))[t] = ((const float4*)(g_mean + (size_t)tpl[i] * AD))[t];
}
__global__ void pad_attr_k(const float* __restrict__ attrs) {
    int i = blockIdx.x, t = threadIdx.x;
    float4 v = make_float4(0.f, 0.f, 0.f, 0.f);
    if (i < C_CLS) v = ((const float4*)(attrs + (size_t)i * AD))[t];
    ((float4*)(g_attr + (size_t)i * AD))[t] = v;
}

// ---------------- transpose (with zero padding of tail rows) -----------------
__global__ __launch_bounds__(256) void transpose_pad_k(const float* __restrict__ in,
                                                       float* __restrict__ out,
                                                       int R, int Rp, int Ccol) {
    __shared__ float t[32][33];
    int bx = blockIdx.x * 32, by = blockIdx.y * 32;
    int x = bx + threadIdx.x;
#pragma unroll
    for (int i = 0; i < 32; i += 8) {
        int y = by + threadIdx.y + i;
        t[threadIdx.y + i][threadIdx.x] = (y < R) ? in[(size_t)y * Ccol + x] : 0.f;
    }
    __syncthreads();
    x = by + threadIdx.x;
#pragma unroll
    for (int i = 0; i < 32; i += 8) {
        int y = bx + threadIdx.y + i;
        out[(size_t)y * Rp + x] = t[threadIdx.x][threadIdx.y + i];
    }
}

// ------ pipelined tf32 HMMA NT GEMM (raw fp32 operands, HW truncation) ------
__global__ __launch_bounds__(128) void mma_gemm_k(const float* __restrict__ A,
                                                  const float* __restrict__ B,
                                                  float* __restrict__ Cc,
                                                  int N, int K, int nch,
                                                  int mstore, int diagflag) {
    extern __shared__ float sm[];
    const int tid = threadIdx.x, wid = tid >> 5, lane = tid & 31;
    const int gid = lane >> 2, tig = lane & 3;
    const int m0 = blockIdx.y * 128, n0 = blockIdx.x * 64;
    const int wm = (wid & 1) * 64, wn = (wid >> 1) * 32;
    const int kbase = blockIdx.z * nch * KCH;
    float* dst = Cc + (size_t)blockIdx.z * CP * N;
    const uint32_t sbase = (uint32_t)__cvta_generic_to_shared(sm);
    const uint32_t* Asm = (const uint32_t*)sm;
    const uint32_t* Bsm = (const uint32_t*)(sm + 2 * 128 * SSTR);

    float acc[4][4][4];
#pragma unroll
    for (int a = 0; a < 4; a++)
#pragma unroll
        for (int b = 0; b < 4; b++)
#pragma unroll
            for (int c = 0; c < 4; c++) acc[a][b][c] = 0.f;

    auto loadc = [&](int kc, int buf) {
        const float* Ab = A + (size_t)m0 * K + kbase + kc * KCH;
        const float* Bb = B + (size_t)n0 * K + kbase + kc * KCH;
        uint32_t as0 = sbase + (uint32_t)(buf * 128 * SSTR) * 4u;
        uint32_t bs0 = sbase + (uint32_t)(2 * 128 * SSTR + buf * 64 * SSTR) * 4u;
#pragma unroll
        for (int i = 0; i < 8; i++) {
            int idx = tid + i * 128;
            int row = idx >> 3, kq = (idx & 7) * 4;
            cp16(as0 + (uint32_t)(row * SSTR + kq) * 4u, Ab + (size_t)row * K + kq);
        }
#pragma unroll
        for (int i = 0; i < 4; i++) {
            int idx = tid + i * 128;
            int row = idx >> 3, kq = (idx & 7) * 4;
            cp16(bs0 + (uint32_t)(row * SSTR + kq) * 4u, Bb + (size_t)row * K + kq);
        }
        asm volatile("cp.async.commit_group;" ::: "memory");
    };
    auto computec = [&](int buf) {
        const uint32_t* Ab = Asm + buf * 128 * SSTR;
        const uint32_t* Bb = Bsm + buf * 64 * SSTR;
#pragma unroll
        for (int ks = 0; ks < 4; ks++) {
            const int kb = ks * 8;
            uint32_t af[4][4], bf[4][2];
#pragma unroll
            for (int mf = 0; mf < 4; mf++) {
                int r = wm + mf * 16 + gid;
                af[mf][0] = Ab[r * SSTR + kb + tig];
                af[mf][1] = Ab[(r + 8) * SSTR + kb + tig];
                af[mf][2] = Ab[r * SSTR + kb + tig + 4];
                af[mf][3] = Ab[(r + 8) * SSTR + kb + tig + 4];
            }
#pragma unroll
            for (int nf = 0; nf < 4; nf++) {
                int r = wn + nf * 8 + gid;
                bf[nf][0] = Bb[r * SSTR + kb + tig];
                bf[nf][1] = Bb[r * SSTR + kb + tig + 4];
            }
#pragma unroll
            for (int mf = 0; mf < 4; mf++)
#pragma unroll
                for (int nf = 0; nf < 4; nf++) mma_tf32(acc[mf][nf], af[mf], bf[nf]);
        }
    };

    loadc(0, 0);
    for (int c = 0; c < nch; c++) {
        if (c + 1 < nch) {
            loadc(c + 1, (c + 1) & 1);
            asm volatile("cp.async.wait_group 1;" ::: "memory");
        } else {
            asm volatile("cp.async.wait_group 0;" ::: "memory");
        }
        __syncthreads();
        computec(c & 1);
        __syncthreads();
    }

#pragma unroll
    for (int mf = 0; mf < 4; mf++) {
#pragma unroll
        for (int nf = 0; nf < 4; nf++) {
            int col = n0 + wn + nf * 8 + tig * 2;
            int r0 = m0 + wm + mf * 16 + gid;
            if (r0 < mstore) {
                *(float2*)(dst + (size_t)r0 * N + col) =
                    make_float2(acc[mf][nf][0], acc[mf][nf][1]);
                if (diagflag) {
                    if (r0 == col)     g_invn[r0] = rsqrtf(fmaxf(acc[mf][nf][0], 1e-30f));
                    if (r0 == col + 1) g_invn[r0] = rsqrtf(fmaxf(acc[mf][nf][1], 1e-30f));
                }
            }
            int r1 = r0 + 8;
            if (r1 < mstore) {
                *(float2*)(dst + (size_t)r1 * N + col) =
                    make_float2(acc[mf][nf][2], acc[mf][nf][3]);
                if (diagflag) {
                    if (r1 == col)     g_invn[r1] = rsqrtf(fmaxf(acc[mf][nf][2], 1e-30f));
                    if (r1 == col + 1) g_invn[r1] = rsqrtf(fmaxf(acc[mf][nf][3], 1e-30f));
                }
            }
        }
    }
}

// ---------------- split-K reduce ---------------------------------------------
__global__ __launch_bounds__(256) void reduce4_k(float* __restrict__ out) {
    int i = blockIdx.x * blockDim.x + threadIdx.x;
    const int n4 = CP * HD / 4;
    if (i < n4) {
        const float4* p = (const float4*)g_part;
        float4 a = p[i], b = p[i + n4], c = p[i + 2 * n4], d = p[i + 3 * n4];
        ((float4*)out)[i] = make_float4(a.x + b.x + c.x + d.x, a.y + b.y + c.y + d.y,
                                        a.z + b.z + c.z + d.z, a.w + b.w + c.w + d.w);
    }
}

// ------- fused masked softmax (on gram) + SpMM: C[r,:] = softmaxrow @ B ------
__global__ __launch_bounds__(256) void softmax_spmm_k(const float* __restrict__ G,
                                                      const float* __restrict__ B,
                                                      float* __restrict__ Cc,
                                                      int mstore) {
    __shared__ float sh[32];
    __shared__ int   scols[CP];
    __shared__ float svals[CP];
    __shared__ int   cnt;
    int r = blockIdx.x;
    int t = threadIdx.x;
    if (r >= mstore) return;
    float2 acc = make_float2(0.f, 0.f);
    if (r < C_CLS) {
        const float* gr = G + (size_t)r * CP;
        float ir = g_invn[r];
        float v[4];
        float mx = -1e30f;
#pragma unroll
        for (int j = 0; j < 4; j++) {
            int c = t + j * 256;
            float x = (c < C_CLS) ? gr[c] * ir * g_invn[c] : -1e30f;
            v[j] = x;
            if (x > 0.5f) mx = fmaxf(mx, x);
        }
        mx = blockMax(mx, sh);
        float m10 = mx * 10.f;
        float e[4];
        float s = 0.f;
#pragma unroll
        for (int j = 0; j < 4; j++) {
            e[j] = (v[j] > 0.5f) ? expf(v[j] * 10.f - m10) : 0.f;
            s += e[j];
        }
        s = blockSum(s, sh);
        float inv = 1.f / s;
        if (t == 0) cnt = 0;
        __syncthreads();
#pragma unroll
        for (int j = 0; j < 4; j++) {
            if (e[j] > 0.f) {
                int slot = atomicAdd(&cnt, 1);
                scols[slot] = t + j * 256;
                svals[slot] = e[j] * inv;
            }
        }
        __syncthreads();
        int n = cnt;
        for (int i = 0; i < n; i++) {
            int c = scols[i];
            float w = svals[i];
            float2 b = ((const float2*)(B + (size_t)c * AD))[t];
            acc.x += w * b.x;
            acc.y += w * b.y;
        }
    }
    ((float2*)(Cc + (size_t)r * AD))[t] = acc;
}

// ---------------- launch ------------------------------------------------------
static float* symf(const void* p) { return (float*)p; }

extern "C" void kernel_launch(void* const* d_in, const int* in_sizes, int n_in,
                              void* d_out, int out_size) {
    const float* img    = (const float*)d_in[0];
    const float* attrs  = (const float*)d_in[1];
    const float* att_g  = (const float*)d_in[2];
    const float* att_h  = (const float*)d_in[3];
    const int*   labels = (const int*)d_in[4];
    const int*   tpl    = (const int*)d_in[5];
    float* out = (float*)d_out;
    int N = in_sizes[4];
    (void)n_in; (void)out_size;

    cudaFuncSetAttribute(mma_gemm_k, cudaFuncAttributeMaxDynamicSharedMemorySize, GSMEM);

    void *p_attr, *p_p, *p_G, *p_enc, *p_q, *p_prot, *p_hT, *p_gT, *p_part,
         *p_counts, *p_cursor;
    cudaGetSymbolAddress(&p_attr, g_attr);
    cudaGetSymbolAddress(&p_p, g_p);
    cudaGetSymbolAddress(&p_G, g_G);
    cudaGetSymbolAddress(&p_enc, g_enc);
    cudaGetSymbolAddress(&p_q, g_q);
    cudaGetSymbolAddress(&p_prot, g_prot);
    cudaGetSymbolAddress(&p_hT, g_hT);
    cudaGetSymbolAddress(&p_gT, g_gT);
    cudaGetSymbolAddress(&p_part, g_part);
    cudaGetSymbolAddress(&p_counts, g_counts);
    cudaGetSymbolAddress(&p_cursor, g_cursor);
    float *A_attr = symf(p_attr), *A_p = symf(p_p), *A_G = symf(p_G),
          *A_enc = symf(p_enc), *A_q = symf(p_q), *A_prot = symf(p_prot),
          *A_hT = symf(p_hT), *A_gT = symf(p_gT), *A_part = symf(p_part);

    cudaStream_t s1;
    cudaStreamCreateWithFlags(&s1, cudaStreamNonBlocking);
    cudaEvent_t evF, evG, evJ;
    cudaEventCreateWithFlags(&evF, cudaEventDisableTiming);
    cudaEventCreateWithFlags(&evG, cudaEventDisableTiming);
    cudaEventCreateWithFlags(&evJ, cudaEventDisableTiming);

    cudaEventRecord(evF, 0);
    cudaStreamWaitEvent(s1, evF, 0);

    // --- side stream: gT transpose + proto pipeline ---
    transpose_pad_k<<<dim3(HD / 32, AD / 32), dim3(32, 8), 0, s1>>>(att_g, A_gT, AD, AD, HD);
    cudaEventRecord(evG, s1);
    cudaMemsetAsync(p_counts, 0, C_CLS * sizeof(int), s1);
    cudaMemsetAsync(p_cursor, 0, C_CLS * sizeof(int), s1);
    hist_k<<<25, 256, 0, s1>>>(labels, N);
    scan_warp_k<<<1, 32, 0, s1>>>();
    scatter_k<<<(N + 255) / 256, 256, 0, s1>>>(labels, N);
    class_mean_k<<<C_CLS, 128, 0, s1>>>(img);
    gather_prot_k<<<C_CLS, 128, 0, s1>>>(tpl);
    cudaEventRecord(evJ, s1);

    // --- main stream: attribute chain ---
    pad_attr_k<<<CP, 128>>>(attrs);
    transpose_pad_k<<<dim3(HD / 32, AD / 32), dim3(32, 8)>>>(att_h, A_hT, AD, AD, HD);

    // p = attr_pad @ att_h  (split-K x4)
    mma_gemm_k<<<dim3(HD / 64, CP / 128, 4), 128, GSMEM>>>(A_attr, A_hT, A_part, HD, AD, 4, CP, 0);
    reduce4_k<<<CP * HD / 4 / 256, 256>>>(A_p);
    // G1 = p @ p^T (fused diag rsqrt)
    mma_gemm_k<<<dim3(CP / 64, CP / 128, 1), 128, GSMEM>>>(A_p, A_p, A_G, CP, HD, 8, CP, 1);
    // enc = softmax(G1) @ attrs  (fused, pad rows zeroed)
    softmax_spmm_k<<<CP, 256>>>(A_G, attrs, A_enc, CP);
    // q = enc @ att_g (split-K x4)
    cudaStreamWaitEvent(0, evG, 0);
    mma_gemm_k<<<dim3(HD / 64, CP / 128, 4), 128, GSMEM>>>(A_enc, A_gT, A_part, HD, AD, 4, CP, 0);
    reduce4_k<<<CP * HD / 4 / 256, 256>>>(A_q);
    // G2 = q @ q^T
    mma_gemm_k<<<dim3(CP / 64, CP / 128, 1), 128, GSMEM>>>(A_q, A_q, A_G, CP, HD, 8, CP, 1);
    // out = softmax(G2) @ protos
    cudaStreamWaitEvent(0, evJ, 0);
    softmax_spmm_k<<<C_CLS, 256>>>(A_G, A_prot, out, C_CLS);
}